// round 2
// baseline (speedup 1.0000x reference)
#include <cuda_runtime.h>
#include <cuda_bf16.h>
#include <math.h>

// ---------------------------------------------------------------------------
// PointNet++ grasp net forward. B=16, N=4096.
// FPS1 -> SA1(ballquery+MLP+max) -> FPS2 -> SA2 -> SA3(GEMMs+max) -> heads
// ---------------------------------------------------------------------------

#define BATCH 16
#define NPTS 4096

// exact f32 thresholds as JAX sees them (python double radius*radius -> f32)
#define R2A ((float)(0.2 * 0.2))
#define R2B ((float)(0.4 * 0.4))

// ------------------------- device scratch (static) -------------------------
__device__ float g_l1x[BATCH * 512 * 3];
__device__ float g_l1f[BATCH * 512 * 128];
__device__ float g_l2x[BATCH * 128 * 3];
__device__ float g_l2f[BATCH * 128 * 256];
__device__ float g_sa3in[BATCH * 128 * 259];
__device__ float g_h3a[BATCH * 128 * 256];
__device__ float g_h3b[BATCH * 128 * 512];
__device__ float g_h3c[BATCH * 128 * 1024];
__device__ float g_g[BATCH * 1024];

// ---------------------------------------------------------------------------
// FPS: one block per batch. phase 0: src = input points (n=4096) -> g_l1x
//      phase 1: src = g_l1x (n=512) -> g_l2x
// Exact jnp semantics: dist init 1e10, far init 0, emit far coords before
// update, argmax with first-index tie-break, distances with no FMA fusion.
// ---------------------------------------------------------------------------
__global__ __launch_bounds__(1024) void fps_kernel(const float* __restrict__ pts_in,
                                                   int n, int S, int phase) {
    const int b = blockIdx.x;
    const float* p = (phase == 0 ? pts_in : g_l1x) + (size_t)b * n * 3;
    float* outxyz = (phase == 0 ? g_l1x : g_l2x);

    const int tid = threadIdx.x, BT = blockDim.x;
    const int PT = n / BT;  // 4 (phase 0) or 1 (phase 1)
    float px[4], py[4], pz[4], dd[4];
#pragma unroll
    for (int k = 0; k < 4; k++) {
        if (k < PT) {
            int i = tid + k * BT;
            px[k] = p[i * 3 + 0];
            py[k] = p[i * 3 + 1];
            pz[k] = p[i * 3 + 2];
            dd[k] = 1e10f;
        }
    }

    __shared__ float sfx, sfy, sfz;
    __shared__ float rv[32];
    __shared__ int ri[32];
    __shared__ int sfar;

    const int lane = tid & 31, wid = tid >> 5, nw = BT >> 5;
    int far = 0;

    for (int s = 0; s < S; s++) {
        if (tid == (far % BT)) {
            int k = far / BT;
            float ox = px[0], oy = py[0], oz = pz[0];
#pragma unroll
            for (int kk = 1; kk < 4; kk++)
                if (kk == k) { ox = px[kk]; oy = py[kk]; oz = pz[kk]; }
            sfx = ox; sfy = oy; sfz = oz;
        }
        __syncthreads();
        const float fx = sfx, fy = sfy, fz = sfz;
        if (tid == 0) {
            float* o = outxyz + ((size_t)b * S + s) * 3;
            o[0] = fx; o[1] = fy; o[2] = fz;
        }
        float bv = -1.0f;
        int bi = 0x7fffffff;
#pragma unroll
        for (int k = 0; k < 4; k++) {
            if (k < PT) {
                float dx = __fsub_rn(px[k], fx);
                float dy = __fsub_rn(py[k], fy);
                float dz = __fsub_rn(pz[k], fz);
                float d = __fadd_rn(__fadd_rn(__fmul_rn(dx, dx), __fmul_rn(dy, dy)),
                                    __fmul_rn(dz, dz));
                float ndv = fminf(dd[k], d);
                dd[k] = ndv;
                if (ndv > bv) { bv = ndv; bi = tid + k * BT; }  // ascending k keeps min idx
            }
        }
        // warp reduce: max val, min idx on tie
#pragma unroll
        for (int off = 16; off > 0; off >>= 1) {
            float ov = __shfl_down_sync(0xffffffffu, bv, off);
            int oi = __shfl_down_sync(0xffffffffu, bi, off);
            if (ov > bv || (ov == bv && oi < bi)) { bv = ov; bi = oi; }
        }
        if (lane == 0) { rv[wid] = bv; ri[wid] = bi; }
        __syncthreads();
        if (wid == 0) {
            float v = (lane < nw) ? rv[lane] : -1.0f;
            int i2 = (lane < nw) ? ri[lane] : 0x7fffffff;
#pragma unroll
            for (int off = 16; off > 0; off >>= 1) {
                float ov = __shfl_down_sync(0xffffffffu, v, off);
                int oi = __shfl_down_sync(0xffffffffu, i2, off);
                if (ov > v || (ov == v && oi < i2)) { v = ov; i2 = oi; }
            }
            if (lane == 0) sfar = i2;
        }
        __syncthreads();
        far = sfar;
    }
}

// ---------------------------------------------------------------------------
// SA1: per (b,s): ball query (r=0.2, ns=32) over 4096 pts, center,
// MLP 3->64->64->128, maxpool over 32 -> g_l1f. Block = 128 threads.
// bias+relu of last layer applied AFTER the max (commutes: relu/+bias monotone).
// ---------------------------------------------------------------------------
__global__ __launch_bounds__(128) void sa1_kernel(
    const float* __restrict__ pts,
    const float* __restrict__ w10, const float* __restrict__ b10,
    const float* __restrict__ w11, const float* __restrict__ b11,
    const float* __restrict__ w12, const float* __restrict__ b12) {
    const int s = blockIdx.x, b = blockIdx.y;
    const int tid = threadIdx.x;
    const float* p = pts + (size_t)b * NPTS * 3;

    __shared__ unsigned smask[128];
    __shared__ int sel[32];
    __shared__ float ctr[3];
    __shared__ float Ax[32 * 3];
    __shared__ float H1[32 * 64];
    __shared__ float H2[32 * 64];
    __shared__ float Hm[4 * 128];

    if (tid < 3) ctr[tid] = g_l1x[((size_t)b * 512 + s) * 3 + tid];
    __syncthreads();
    const float cx = ctr[0], cy = ctr[1], cz = ctr[2];

    // in-radius bitmask, index-ordered
    const int lane = tid & 31, wid = tid >> 5;
    for (int w = wid; w < 128; w += 4) {
        int j = w * 32 + lane;
        float dx = __fsub_rn(cx, p[j * 3 + 0]);
        float dy = __fsub_rn(cy, p[j * 3 + 1]);
        float dz = __fsub_rn(cz, p[j * 3 + 2]);
        float d = __fadd_rn(__fadd_rn(__fmul_rn(dx, dx), __fmul_rn(dy, dy)),
                            __fmul_rn(dz, dz));
        unsigned m = __ballot_sync(0xffffffffu, !(d > R2A));
        if (lane == 0) smask[w] = m;
    }
    __syncthreads();
    if (tid == 0) {
        int cnt = 0;
        for (int w = 0; w < 128 && cnt < 32; w++) {
            unsigned m = smask[w];
            while (m && cnt < 32) {
                int t = __ffs(m) - 1;
                m &= m - 1;
                sel[cnt++] = w * 32 + t;
            }
        }
        int c0 = sel[0];
        for (int j = cnt; j < 32; j++) sel[j] = c0;
    }
    __syncthreads();
    if (tid < 96) {
        int n = tid / 3, c = tid - n * 3;
        float cc = (c == 0) ? cx : ((c == 1) ? cy : cz);
        Ax[tid] = p[sel[n] * 3 + c] - cc;
    }
    __syncthreads();

    // L1: 3 -> 64
#pragma unroll
    for (int r = 0; r < 16; r++) {
        int lin = r * 128 + tid;
        int n = lin >> 6, o = lin & 63;
        float a = b10[o] + Ax[n * 3 + 0] * w10[o] + Ax[n * 3 + 1] * w10[64 + o] +
                  Ax[n * 3 + 2] * w10[128 + o];
        H1[lin] = fmaxf(a, 0.f);
    }
    __syncthreads();

    // L2: 64 -> 64 (tile 4n x 4o)
    {
        const int o0 = (tid & 15) * 4, n0 = (tid >> 4) * 4;
        float acc[4][4] = {};
        for (int c = 0; c < 64; c++) {
            float4 bvv = *(const float4*)(w11 + c * 64 + o0);
#pragma unroll
            for (int i = 0; i < 4; i++) {
                float a = H1[(n0 + i) * 64 + c];
                acc[i][0] += a * bvv.x; acc[i][1] += a * bvv.y;
                acc[i][2] += a * bvv.z; acc[i][3] += a * bvv.w;
            }
        }
#pragma unroll
        for (int i = 0; i < 4; i++)
#pragma unroll
            for (int j = 0; j < 4; j++)
                H2[(n0 + i) * 64 + o0 + j] = fmaxf(acc[i][j] + b11[o0 + j], 0.f);
    }
    __syncthreads();

    // L3: 64 -> 128 with fused partial maxpool (tile 8n x 4o)
    {
        const int o0 = (tid & 31) * 4, nm = tid >> 5, n0 = nm * 8;
        float acc[8][4] = {};
        for (int c = 0; c < 64; c++) {
            float4 bvv = *(const float4*)(w12 + c * 128 + o0);
#pragma unroll
            for (int i = 0; i < 8; i++) {
                float a = H2[(n0 + i) * 64 + c];
                acc[i][0] += a * bvv.x; acc[i][1] += a * bvv.y;
                acc[i][2] += a * bvv.z; acc[i][3] += a * bvv.w;
            }
        }
#pragma unroll
        for (int j = 0; j < 4; j++) {
            float m = acc[0][j];
#pragma unroll
            for (int i = 1; i < 8; i++) m = fmaxf(m, acc[i][j]);
            Hm[nm * 128 + o0 + j] = m;
        }
    }
    __syncthreads();
    if (tid < 128) {
        float m = fmaxf(fmaxf(Hm[tid], Hm[128 + tid]), fmaxf(Hm[256 + tid], Hm[384 + tid]));
        g_l1f[((size_t)b * 512 + s) * 128 + tid] = fmaxf(m + b12[tid], 0.f);
    }
}

// ---------------------------------------------------------------------------
// SA2: per (b,s): ball query (r=0.4, ns=64) over 512 pts, feats = [cxyz,l1f],
// MLP 131->128->128->256, maxpool over 64 -> g_l2f. Block = 256, dyn smem.
// ---------------------------------------------------------------------------
extern __shared__ float sa2_sm[];

__global__ __launch_bounds__(256) void sa2_kernel(
    const float* __restrict__ w20, const float* __restrict__ b20,
    const float* __restrict__ w21, const float* __restrict__ b21,
    const float* __restrict__ w22, const float* __restrict__ b22) {
    const int s = blockIdx.x, b = blockIdx.y;
    const int tid = threadIdx.x;
    const float* px = g_l1x + (size_t)b * 512 * 3;

    __shared__ unsigned smask[16];
    __shared__ int sel[64];
    __shared__ float ctr[3];
    float* Ab = sa2_sm;             // 64*131: input A; later reused as H2 (pitch 128)
    float* Hb = sa2_sm + 64 * 131;  // 64*128: H1; later partial max (4*256)

    if (tid < 3) ctr[tid] = g_l2x[((size_t)b * 128 + s) * 3 + tid];
    __syncthreads();
    const float cx = ctr[0], cy = ctr[1], cz = ctr[2];

    const int lane = tid & 31, wid = tid >> 5;
    for (int w = wid; w < 16; w += 8) {
        int j = w * 32 + lane;
        float dx = __fsub_rn(cx, px[j * 3 + 0]);
        float dy = __fsub_rn(cy, px[j * 3 + 1]);
        float dz = __fsub_rn(cz, px[j * 3 + 2]);
        float d = __fadd_rn(__fadd_rn(__fmul_rn(dx, dx), __fmul_rn(dy, dy)),
                            __fmul_rn(dz, dz));
        unsigned m = __ballot_sync(0xffffffffu, !(d > R2B));
        if (lane == 0) smask[w] = m;
    }
    __syncthreads();
    if (tid == 0) {
        int cnt = 0;
        for (int w = 0; w < 16 && cnt < 64; w++) {
            unsigned m = smask[w];
            while (m && cnt < 64) {
                int t = __ffs(m) - 1;
                m &= m - 1;
                sel[cnt++] = w * 32 + t;
            }
        }
        int c0 = sel[0];
        for (int j = cnt; j < 64; j++) sel[j] = c0;
    }
    __syncthreads();
    if (tid < 192) {
        int n = tid / 3, c = tid - n * 3;
        float cc = (c == 0) ? cx : ((c == 1) ? cy : cz);
        Ab[n * 131 + c] = px[sel[n] * 3 + c] - cc;
    }
    for (int e = tid; e < 64 * 128; e += 256) {
        int n = e >> 7, c = e & 127;
        Ab[n * 131 + 3 + c] = g_l1f[((size_t)b * 512 + sel[n]) * 128 + c];
    }
    __syncthreads();

    // L1: 131 -> 128 (tile 8n x 4o)
    {
        const int o0 = (tid & 31) * 4, n0 = (tid >> 5) * 8;
        float acc[8][4] = {};
        for (int c = 0; c < 131; c++) {
            float4 bvv = *(const float4*)(w20 + c * 128 + o0);
#pragma unroll
            for (int i = 0; i < 8; i++) {
                float a = Ab[(n0 + i) * 131 + c];
                acc[i][0] += a * bvv.x; acc[i][1] += a * bvv.y;
                acc[i][2] += a * bvv.z; acc[i][3] += a * bvv.w;
            }
        }
#pragma unroll
        for (int i = 0; i < 8; i++)
#pragma unroll
            for (int j = 0; j < 4; j++)
                Hb[(n0 + i) * 128 + o0 + j] = fmaxf(acc[i][j] + b20[o0 + j], 0.f);
    }
    __syncthreads();

    // L2: 128 -> 128, reads Hb, writes Ab region (pitch 128). A is dead now.
    {
        const int o0 = (tid & 31) * 4, n0 = (tid >> 5) * 8;
        float acc[8][4] = {};
        for (int c = 0; c < 128; c++) {
            float4 bvv = *(const float4*)(w21 + c * 128 + o0);
#pragma unroll
            for (int i = 0; i < 8; i++) {
                float a = Hb[(n0 + i) * 128 + c];
                acc[i][0] += a * bvv.x; acc[i][1] += a * bvv.y;
                acc[i][2] += a * bvv.z; acc[i][3] += a * bvv.w;
            }
        }
#pragma unroll
        for (int i = 0; i < 8; i++)
#pragma unroll
            for (int j = 0; j < 4; j++)
                Ab[(n0 + i) * 128 + o0 + j] = fmaxf(acc[i][j] + b21[o0 + j], 0.f);
    }
    __syncthreads();

    // L3: 128 -> 256 with fused partial maxpool (tile 16n x 4o); partials in Hb
    {
        const int o0 = (tid & 63) * 4, nm = tid >> 6, n0 = nm * 16;
        float acc[16][4] = {};
        for (int c = 0; c < 128; c++) {
            float4 bvv = *(const float4*)(w22 + c * 256 + o0);
#pragma unroll
            for (int i = 0; i < 16; i++) {
                float a = Ab[(n0 + i) * 128 + c];
                acc[i][0] += a * bvv.x; acc[i][1] += a * bvv.y;
                acc[i][2] += a * bvv.z; acc[i][3] += a * bvv.w;
            }
        }
        __syncthreads();
#pragma unroll
        for (int j = 0; j < 4; j++) {
            float m = acc[0][j];
#pragma unroll
            for (int i = 1; i < 16; i++) m = fmaxf(m, acc[i][j]);
            Hb[nm * 256 + o0 + j] = m;
        }
    }
    __syncthreads();
    {
        int o = tid;
        float m = fmaxf(fmaxf(Hb[o], Hb[256 + o]), fmaxf(Hb[512 + o], Hb[768 + o]));
        g_l2f[((size_t)b * 128 + s) * 256 + o] = fmaxf(m + b22[o], 0.f);
    }
}

// ---------------------------------------------------------------------------
// SA3 input build: concat(l2x, l2f) -> [B,128,259]
// ---------------------------------------------------------------------------
__global__ __launch_bounds__(256) void sa3build_kernel() {
    const int b = blockIdx.x;
    for (int e = threadIdx.x; e < 128 * 259; e += blockDim.x) {
        int n = e / 259, c = e - n * 259;
        g_sa3in[(size_t)b * 128 * 259 + e] =
            (c < 3) ? g_l2x[((size_t)b * 128 + n) * 3 + c]
                    : g_l2f[((size_t)b * 128 + n) * 256 + (c - 3)];
    }
}

// ---------------------------------------------------------------------------
// Generic GEMM + bias + relu: C[b] = relu(A[b] @ W + bias). M = 128.
// grid (B, 2, O/64), block 256, tile 4n x 4o, K staged in 32-wide smem tiles.
// which: 0 sa3in->h3a (K=259), 1 h3a->h3b (256), 2 h3b->h3c (512)
// ---------------------------------------------------------------------------
__global__ __launch_bounds__(256) void gemm_relu_kernel(const float* __restrict__ W,
                                                        const float* __restrict__ bias,
                                                        int K, int O, int which) {
    const int b = blockIdx.x, mblk = blockIdx.y, oblk = blockIdx.z;
    const float* A;
    float* C;
    if (which == 0) { A = g_sa3in; C = g_h3a; }
    else if (which == 1) { A = g_h3a; C = g_h3b; }
    else { A = g_h3b; C = g_h3c; }
    const float* Abase = A + (size_t)b * 128 * K;
    float* Cbase = C + (size_t)b * 128 * O;

    const int tid = threadIdx.x;
    const int o0 = oblk * 64 + (tid & 15) * 4;
    const int nl0 = (tid >> 4) * 4;  // local row in 64-row tile

    __shared__ float As[64 * 32];
    float acc[4][4] = {};
    for (int kb = 0; kb < K; kb += 32) {
        const int w = min(32, K - kb);
        __syncthreads();
        for (int e = tid; e < 64 * 32; e += 256) {
            int r = e >> 5, cc = e & 31;
            As[e] = (cc < w) ? Abase[(size_t)(mblk * 64 + r) * K + kb + cc] : 0.f;
        }
        __syncthreads();
        for (int c = 0; c < w; c++) {
            float4 bvv = *(const float4*)(W + (size_t)(kb + c) * O + o0);
#pragma unroll
            for (int i = 0; i < 4; i++) {
                float a = As[(nl0 + i) * 32 + c];
                acc[i][0] += a * bvv.x; acc[i][1] += a * bvv.y;
                acc[i][2] += a * bvv.z; acc[i][3] += a * bvv.w;
            }
        }
    }
    const int n0 = mblk * 64 + nl0;
#pragma unroll
    for (int i = 0; i < 4; i++)
#pragma unroll
        for (int j = 0; j < 4; j++)
            Cbase[(size_t)(n0 + i) * O + o0 + j] = fmaxf(acc[i][j] + bias[o0 + j], 0.f);
}

// ---------------------------------------------------------------------------
// Maxpool over the 128 rows of h3c -> g_g [B,1024]
// ---------------------------------------------------------------------------
__global__ __launch_bounds__(128) void maxpool_kernel() {
    const int b = blockIdx.x;
    const int o = blockIdx.y * 128 + threadIdx.x;
    float m = -1e30f;
    for (int n = 0; n < 128; n++)
        m = fmaxf(m, g_h3c[((size_t)b * 128 + n) * 1024 + o]);
    g_g[b * 1024 + o] = m;
}

// ---------------------------------------------------------------------------
// Heads: label = sigmoid(relu(g@lw1+lb1)@lw2+lb2); res = relu(g@fw1+fb1)@fw2+fb2
// out = [label(2), pl(3), rl(6), pr(3), rr(6)] per batch row.
// ---------------------------------------------------------------------------
__global__ __launch_bounds__(256) void heads_kernel(
    const float* __restrict__ lw1, const float* __restrict__ lb1,
    const float* __restrict__ lw2, const float* __restrict__ lb2,
    const float* __restrict__ fw1, const float* __restrict__ fb1,
    const float* __restrict__ fw2, const float* __restrict__ fb2,
    const float* __restrict__ pos_mean, const float* __restrict__ pos_std,
    const float* __restrict__ rot_mean, const float* __restrict__ rot_std,
    float* __restrict__ out) {
    const int b = blockIdx.x;
    const int tid = threadIdx.x;
    __shared__ float gs[1024], h1s[256], f1s[512], res[18], lab[2];
    for (int e = tid; e < 1024; e += 256) gs[e] = g_g[b * 1024 + e];
    __syncthreads();
#pragma unroll
    for (int rep = 0; rep < 2; rep++) {
        int o = tid + rep * 256;
        float acc = fb1[o];
        for (int k = 0; k < 1024; k++) acc += gs[k] * fw1[k * 512 + o];
        f1s[o] = fmaxf(acc, 0.f);
    }
    {
        int o = tid;
        float acc = lb1[o];
        for (int k = 0; k < 1024; k++) acc += gs[k] * lw1[k * 256 + o];
        h1s[o] = fmaxf(acc, 0.f);
    }
    __syncthreads();
    if (tid < 18) {
        float acc = fb2[tid];
        for (int k = 0; k < 512; k++) acc += f1s[k] * fw2[k * 18 + tid];
        res[tid] = acc;
    } else if (tid < 20) {
        int j = tid - 18;
        float acc = lb2[j];
        for (int k = 0; k < 256; k++) acc += h1s[k] * lw2[k * 2 + j];
        lab[j] = 1.f / (1.f + expf(-acc));
    }
    __syncthreads();
    if (tid < 20) {
        float v;
        if (tid < 2) v = lab[tid];
        else if (tid < 5) { int i = tid - 2; v = res[i] * pos_std[i] + pos_mean[i]; }
        else if (tid < 11) { int i = tid - 5; v = res[3 + i] * rot_std[i] + rot_mean[i]; }
        else if (tid < 14) { int i = tid - 11; v = res[9 + i] * pos_std[i] + pos_mean[i]; }
        else { int i = tid - 14; v = res[12 + i] * rot_std[i] + rot_mean[i]; }
        out[b * 20 + tid] = v;
    }
}

// ---------------------------------------------------------------------------
extern "C" void kernel_launch(void* const* d_in, const int* in_sizes, int n_in,
                              void* d_out, int out_size) {
    (void)in_sizes; (void)n_in; (void)out_size;
    const float* pts = (const float*)d_in[0];
    const float* w10 = (const float*)d_in[1];  const float* b10 = (const float*)d_in[2];
    const float* w11 = (const float*)d_in[3];  const float* b11 = (const float*)d_in[4];
    const float* w12 = (const float*)d_in[5];  const float* b12 = (const float*)d_in[6];
    const float* w20 = (const float*)d_in[7];  const float* b20 = (const float*)d_in[8];
    const float* w21 = (const float*)d_in[9];  const float* b21 = (const float*)d_in[10];
    const float* w22 = (const float*)d_in[11]; const float* b22 = (const float*)d_in[12];
    const float* w30 = (const float*)d_in[13]; const float* b30 = (const float*)d_in[14];
    const float* w31 = (const float*)d_in[15]; const float* b31 = (const float*)d_in[16];
    const float* w32 = (const float*)d_in[17]; const float* b32 = (const float*)d_in[18];
    const float* lw1 = (const float*)d_in[19]; const float* lb1 = (const float*)d_in[20];
    const float* lw2 = (const float*)d_in[21]; const float* lb2 = (const float*)d_in[22];
    const float* fw1 = (const float*)d_in[23]; const float* fb1 = (const float*)d_in[24];
    const float* fw2 = (const float*)d_in[25]; const float* fb2 = (const float*)d_in[26];
    const float* pos_mean = (const float*)d_in[27];
    const float* pos_std  = (const float*)d_in[28];
    const float* rot_mean = (const float*)d_in[29];
    const float* rot_std  = (const float*)d_in[30];
    float* out = (float*)d_out;

    const int sa2_smem = (64 * 131 + 64 * 128) * (int)sizeof(float);  // 66304 B
    cudaFuncSetAttribute(sa2_kernel, cudaFuncAttributeMaxDynamicSharedMemorySize, sa2_smem);

    fps_kernel<<<BATCH, 1024>>>(pts, NPTS, 512, 0);
    sa1_kernel<<<dim3(512, BATCH), 128>>>(pts, w10, b10, w11, b11, w12, b12);
    fps_kernel<<<BATCH, 512>>>(pts, 512, 128, 1);
    sa2_kernel<<<dim3(128, BATCH), 256, sa2_smem>>>(w20, b20, w21, b21, w22, b22);
    sa3build_kernel<<<BATCH, 256>>>();
    gemm_relu_kernel<<<dim3(BATCH, 2, 4), 256>>>(w30, b30, 259, 256, 0);
    gemm_relu_kernel<<<dim3(BATCH, 2, 8), 256>>>(w31, b31, 256, 512, 1);
    gemm_relu_kernel<<<dim3(BATCH, 2, 16), 256>>>(w32, b32, 512, 1024, 2);
    maxpool_kernel<<<dim3(BATCH, 8), 128>>>();
    heads_kernel<<<BATCH, 256>>>(lw1, lb1, lw2, lb2, fw1, fb1, fw2, fb2,
                                 pos_mean, pos_std, rot_mean, rot_std, out);
}

// round 4
// speedup vs baseline: 1.5683x; 1.5683x over previous
#include <cuda_runtime.h>
#include <cuda_bf16.h>
#include <math.h>

// ---------------------------------------------------------------------------
// PointNet++ grasp net forward. B=16, N=4096.
// FPS1 -> SA1 -> FPS2 -> U2-precompute -> SA2 -> SA3(GEMMs+max) -> heads
// ---------------------------------------------------------------------------

#define BATCH 16
#define NPTS 4096

// exact f32 thresholds as JAX sees them (python double radius*radius -> f32)
#define R2A ((float)(0.2 * 0.2))
#define R2B ((float)(0.4 * 0.4))

// ------------------------- device scratch (static) -------------------------
__device__ __align__(16) float g_l1x[BATCH * 512 * 3];
__device__ __align__(16) float g_l1f[BATCH * 512 * 128];
__device__ __align__(16) float g_u2[BATCH * 512 * 128];   // l1f @ w20[3:] + b20
__device__ __align__(16) float g_l2x[BATCH * 128 * 3];
__device__ __align__(16) float g_l2f[BATCH * 128 * 256];
__device__ __align__(16) float g_sa3in[BATCH * 128 * 259];
__device__ __align__(16) float g_h3a[BATCH * 128 * 256];
__device__ __align__(16) float g_h3b[BATCH * 128 * 512];
__device__ __align__(16) float g_h3c[BATCH * 128 * 1024];
__device__ __align__(16) float g_g[BATCH * 1024];

// ---------------------------------------------------------------------------
// FPS: one block per batch. phase 0: src = input points (n=4096) -> g_l1x
//      phase 1: src = g_l1x (n=512) -> g_l2x
// Points cached in dynamic smem so the "far" broadcast is a plain LDS:
// 2 barriers per iteration. Exact jnp semantics preserved (dist init 1e10,
// first-index tie-break, no FMA contraction in distances).
// ---------------------------------------------------------------------------
extern __shared__ float fps_sm[];

__global__ __launch_bounds__(1024) void fps_kernel(const float* __restrict__ pts_in,
                                                   int n, int S, int phase) {
    const int b = blockIdx.x;
    const float* p = (phase == 0 ? pts_in : g_l1x) + (size_t)b * n * 3;
    float* outxyz = (phase == 0 ? g_l1x : g_l2x);

    const int tid = threadIdx.x, BT = blockDim.x;
    float* sp = fps_sm;              // n*3
    float* rv = fps_sm + n * 3;      // 32
    int* ri = (int*)(rv + 32);       // 32
    int* sfar = ri + 32;

    for (int e = tid; e < n * 3; e += BT) sp[e] = p[e];

    const int PT = n / BT;  // 4 (phase 0) or 1 (phase 1)
    float px[4], py[4], pz[4], dd[4];
#pragma unroll
    for (int k = 0; k < 4; k++) {
        if (k < PT) {
            int i = tid + k * BT;
            px[k] = p[i * 3 + 0];
            py[k] = p[i * 3 + 1];
            pz[k] = p[i * 3 + 2];
            dd[k] = 1e10f;
        }
    }
    __syncthreads();

    const int lane = tid & 31, wid = tid >> 5, nw = BT >> 5;
    int far = 0;

    for (int s = 0; s < S; s++) {
        const float fx = sp[far * 3 + 0], fy = sp[far * 3 + 1], fz = sp[far * 3 + 2];
        if (tid == 0) {
            float* o = outxyz + ((size_t)b * S + s) * 3;
            o[0] = fx; o[1] = fy; o[2] = fz;
        }
        float bv = -1.0f;
        int bi = 0x7fffffff;
#pragma unroll
        for (int k = 0; k < 4; k++) {
            if (k < PT) {
                float dx = __fsub_rn(px[k], fx);
                float dy = __fsub_rn(py[k], fy);
                float dz = __fsub_rn(pz[k], fz);
                float d = __fadd_rn(__fadd_rn(__fmul_rn(dx, dx), __fmul_rn(dy, dy)),
                                    __fmul_rn(dz, dz));
                float ndv = fminf(dd[k], d);
                dd[k] = ndv;
                if (ndv > bv) { bv = ndv; bi = tid + k * BT; }  // ascending k keeps min idx
            }
        }
        // warp reduce: max val, min idx on tie
#pragma unroll
        for (int off = 16; off > 0; off >>= 1) {
            float ov = __shfl_down_sync(0xffffffffu, bv, off);
            int oi = __shfl_down_sync(0xffffffffu, bi, off);
            if (ov > bv || (ov == bv && oi < bi)) { bv = ov; bi = oi; }
        }
        if (lane == 0) { rv[wid] = bv; ri[wid] = bi; }
        __syncthreads();
        if (wid == 0) {
            float v = (lane < nw) ? rv[lane] : -1.0f;
            int i2 = (lane < nw) ? ri[lane] : 0x7fffffff;
#pragma unroll
            for (int off = 16; off > 0; off >>= 1) {
                float ov = __shfl_down_sync(0xffffffffu, v, off);
                int oi = __shfl_down_sync(0xffffffffu, i2, off);
                if (ov > v || (ov == v && oi < i2)) { v = ov; i2 = oi; }
            }
            if (lane == 0) *sfar = i2;
        }
        __syncthreads();
        far = *sfar;
    }
}

// ---------------------------------------------------------------------------
// SA1: per (b,s): ball query (r=0.2, ns=32) over 4096 pts, center,
// MLP 3->64->64->128, maxpool over 32 -> g_l1f. Block = 128 threads.
// ---------------------------------------------------------------------------
#define P1 68  // padded pitch for 64-wide smem rows

__global__ __launch_bounds__(128) void sa1_kernel(
    const float* __restrict__ pts,
    const float* __restrict__ w10, const float* __restrict__ b10,
    const float* __restrict__ w11, const float* __restrict__ b11,
    const float* __restrict__ w12, const float* __restrict__ b12) {
    const int s = blockIdx.x, b = blockIdx.y;
    const int tid = threadIdx.x;
    const float* p = pts + (size_t)b * NPTS * 3;

    __shared__ unsigned smask[128];
    __shared__ int sel[32];
    __shared__ float ctr[3];
    __shared__ float Ax[32 * 3];
    __shared__ float H1[32 * P1];
    __shared__ float H2[32 * P1];
    __shared__ float Pm[8 * 128];

    if (tid < 3) ctr[tid] = g_l1x[((size_t)b * 512 + s) * 3 + tid];
    __syncthreads();
    const float cx = ctr[0], cy = ctr[1], cz = ctr[2];

    const int lane = tid & 31, wid = tid >> 5;
    for (int w = wid; w < 128; w += 4) {
        int j = w * 32 + lane;
        float dx = __fsub_rn(cx, p[j * 3 + 0]);
        float dy = __fsub_rn(cy, p[j * 3 + 1]);
        float dz = __fsub_rn(cz, p[j * 3 + 2]);
        float d = __fadd_rn(__fadd_rn(__fmul_rn(dx, dx), __fmul_rn(dy, dy)),
                            __fmul_rn(dz, dz));
        unsigned m = __ballot_sync(0xffffffffu, !(d > R2A));
        if (lane == 0) smask[w] = m;
    }
    __syncthreads();
    if (tid == 0) {
        int cnt = 0;
        for (int w = 0; w < 128 && cnt < 32; w++) {
            unsigned m = smask[w];
            while (m && cnt < 32) {
                int t = __ffs(m) - 1;
                m &= m - 1;
                sel[cnt++] = w * 32 + t;
            }
        }
        int c0 = sel[0];
        for (int j = cnt; j < 32; j++) sel[j] = c0;
    }
    __syncthreads();
    if (tid < 96) {
        int n = tid / 3, c = tid - n * 3;
        float cc = (c == 0) ? cx : ((c == 1) ? cy : cz);
        Ax[tid] = p[sel[n] * 3 + c] - cc;
    }
    __syncthreads();

    // L1: 3 -> 64
#pragma unroll
    for (int r = 0; r < 16; r++) {
        int lin = r * 128 + tid;
        int n = lin >> 6, o = lin & 63;
        float a = b10[o] + Ax[n * 3 + 0] * w10[o] + Ax[n * 3 + 1] * w10[64 + o] +
                  Ax[n * 3 + 2] * w10[128 + o];
        H1[n * P1 + o] = fmaxf(a, 0.f);
    }
    __syncthreads();

    // L2: 64 -> 64 (tile 4n x 4o)
    {
        const int o0 = (tid & 15) * 4, n0 = (tid >> 4) * 4;
        float acc[4][4] = {};
        for (int c = 0; c < 64; c++) {
            float4 bvv = *(const float4*)(w11 + c * 64 + o0);
#pragma unroll
            for (int i = 0; i < 4; i++) {
                float a = H1[(n0 + i) * P1 + c];
                acc[i][0] += a * bvv.x; acc[i][1] += a * bvv.y;
                acc[i][2] += a * bvv.z; acc[i][3] += a * bvv.w;
            }
        }
#pragma unroll
        for (int i = 0; i < 4; i++)
#pragma unroll
            for (int j = 0; j < 4; j++)
                H2[(n0 + i) * P1 + o0 + j] = fmaxf(acc[i][j] + b11[o0 + j], 0.f);
    }
    __syncthreads();

    // L3: 64 -> 128 with fused partial maxpool (tile 4n x 8o)
    {
        const int o0 = (tid & 15) * 8, ng = tid >> 4, n0 = ng * 4;
        float acc[4][8] = {};
        for (int c = 0; c < 64; c++) {
            float4 b0 = *(const float4*)(w12 + c * 128 + o0);
            float4 b1 = *(const float4*)(w12 + c * 128 + o0 + 4);
#pragma unroll
            for (int i = 0; i < 4; i++) {
                float a = H2[(n0 + i) * P1 + c];
                acc[i][0] += a * b0.x; acc[i][1] += a * b0.y;
                acc[i][2] += a * b0.z; acc[i][3] += a * b0.w;
                acc[i][4] += a * b1.x; acc[i][5] += a * b1.y;
                acc[i][6] += a * b1.z; acc[i][7] += a * b1.w;
            }
        }
#pragma unroll
        for (int j = 0; j < 8; j++) {
            float m = acc[0][j];
#pragma unroll
            for (int i = 1; i < 4; i++) m = fmaxf(m, acc[i][j]);
            Pm[ng * 128 + o0 + j] = m;
        }
    }
    __syncthreads();
    if (tid < 128) {
        float m = Pm[tid];
#pragma unroll
        for (int g = 1; g < 8; g++) m = fmaxf(m, Pm[g * 128 + tid]);
        g_l1f[((size_t)b * 512 + s) * 128 + tid] = fmaxf(m + b12[tid], 0.f);
    }
}

// ---------------------------------------------------------------------------
// SA2: per (b,s): ball query (r=0.4, ns=64) over 512 pts.
// L1 via precomputed U2 gather: h1 = relu(dxyz @ w20[0:3] + U2[sel])
// then 128->128, 128->256 + maxpool. Block = 256 threads, static smem.
// H is 16B-aligned (float4 access); all vector offsets are multiples of 4 floats.
// ---------------------------------------------------------------------------
#define P2 132  // padded pitch (mod 4 == 0) for 128-wide smem rows

__global__ __launch_bounds__(256) void sa2_kernel(
    const float* __restrict__ w20,
    const float* __restrict__ w21, const float* __restrict__ b21,
    const float* __restrict__ w22, const float* __restrict__ b22) {
    const int s = blockIdx.x, b = blockIdx.y;
    const int tid = threadIdx.x;
    const float* px = g_l1x + (size_t)b * 512 * 3;

    __shared__ __align__(16) float H[64 * P2];  // H1 -> H2 -> partial maxes [8][256]
    __shared__ unsigned smask[16];
    __shared__ int sel[64];
    __shared__ float ctr[3];
    __shared__ float dx3[64 * 3];

    if (tid < 3) ctr[tid] = g_l2x[((size_t)b * 128 + s) * 3 + tid];
    __syncthreads();
    const float cx = ctr[0], cy = ctr[1], cz = ctr[2];

    const int lane = tid & 31, wid = tid >> 5;
    for (int w = wid; w < 16; w += 8) {
        int j = w * 32 + lane;
        float dx = __fsub_rn(cx, px[j * 3 + 0]);
        float dy = __fsub_rn(cy, px[j * 3 + 1]);
        float dz = __fsub_rn(cz, px[j * 3 + 2]);
        float d = __fadd_rn(__fadd_rn(__fmul_rn(dx, dx), __fmul_rn(dy, dy)),
                            __fmul_rn(dz, dz));
        unsigned m = __ballot_sync(0xffffffffu, !(d > R2B));
        if (lane == 0) smask[w] = m;
    }
    __syncthreads();
    if (tid == 0) {
        int cnt = 0;
        for (int w = 0; w < 16 && cnt < 64; w++) {
            unsigned m = smask[w];
            while (m && cnt < 64) {
                int t = __ffs(m) - 1;
                m &= m - 1;
                sel[cnt++] = w * 32 + t;
            }
        }
        int c0 = sel[0];
        for (int j = cnt; j < 64; j++) sel[j] = c0;
    }
    __syncthreads();
    if (tid < 192) {
        int n = tid / 3, c = tid - n * 3;
        float cc = (c == 0) ? cx : ((c == 1) ? cy : cz);
        dx3[tid] = px[sel[n] * 3 + c] - cc;
    }
    __syncthreads();

    // L1: gather U2 + xyz contribution, relu. 8n x 4o per thread.
    {
        const int o0 = (tid & 31) * 4, n0 = (tid >> 5) * 8;
        float4 wxv = *(const float4*)(w20 + o0);
        float4 wyv = *(const float4*)(w20 + 128 + o0);
        float4 wzv = *(const float4*)(w20 + 256 + o0);
#pragma unroll
        for (int i = 0; i < 8; i++) {
            int n = n0 + i;
            float ddx = dx3[n * 3 + 0], ddy = dx3[n * 3 + 1], ddz = dx3[n * 3 + 2];
            float4 u = *(const float4*)(g_u2 + ((size_t)b * 512 + sel[n]) * 128 + o0);
            float4 r;
            r.x = fmaxf(u.x + ddx * wxv.x + ddy * wyv.x + ddz * wzv.x, 0.f);
            r.y = fmaxf(u.y + ddx * wxv.y + ddy * wyv.y + ddz * wzv.y, 0.f);
            r.z = fmaxf(u.z + ddx * wxv.z + ddy * wyv.z + ddz * wzv.z, 0.f);
            r.w = fmaxf(u.w + ddx * wxv.w + ddy * wyv.w + ddz * wzv.w, 0.f);
            *(float4*)(H + n * P2 + o0) = r;
        }
    }
    __syncthreads();

    // L2: 128 -> 128 (tile 4n x 8o), accumulate in regs, then overwrite H
    {
        const int o0 = (tid & 15) * 8, n0 = (tid >> 4) * 4;
        float acc[4][8] = {};
        for (int c = 0; c < 128; c++) {
            float4 b0 = *(const float4*)(w21 + c * 128 + o0);
            float4 b1 = *(const float4*)(w21 + c * 128 + o0 + 4);
#pragma unroll
            for (int i = 0; i < 4; i++) {
                float a = H[(n0 + i) * P2 + c];
                acc[i][0] += a * b0.x; acc[i][1] += a * b0.y;
                acc[i][2] += a * b0.z; acc[i][3] += a * b0.w;
                acc[i][4] += a * b1.x; acc[i][5] += a * b1.y;
                acc[i][6] += a * b1.z; acc[i][7] += a * b1.w;
            }
        }
        __syncthreads();
#pragma unroll
        for (int i = 0; i < 4; i++)
#pragma unroll
            for (int j = 0; j < 8; j++)
                H[(n0 + i) * P2 + o0 + j] = fmaxf(acc[i][j] + b21[o0 + j], 0.f);
    }
    __syncthreads();

    // L3: 128 -> 256 with fused partial maxpool (tile 8n x 8o)
    {
        const int o0 = (tid & 31) * 8, ng = tid >> 5, n0 = ng * 8;
        float acc[8][8] = {};
        for (int c = 0; c < 128; c++) {
            float4 b0 = *(const float4*)(w22 + c * 256 + o0);
            float4 b1 = *(const float4*)(w22 + c * 256 + o0 + 4);
#pragma unroll
            for (int i = 0; i < 8; i++) {
                float a = H[(n0 + i) * P2 + c];
                acc[i][0] += a * b0.x; acc[i][1] += a * b0.y;
                acc[i][2] += a * b0.z; acc[i][3] += a * b0.w;
                acc[i][4] += a * b1.x; acc[i][5] += a * b1.y;
                acc[i][6] += a * b1.z; acc[i][7] += a * b1.w;
            }
        }
        __syncthreads();
#pragma unroll
        for (int j = 0; j < 8; j++) {
            float m = acc[0][j];
#pragma unroll
            for (int i = 1; i < 8; i++) m = fmaxf(m, acc[i][j]);
            H[ng * 256 + o0 + j] = m;  // reuse H as Pm[8][256]
        }
    }
    __syncthreads();
    {
        int o = tid;
        float m = H[o];
#pragma unroll
        for (int g = 1; g < 8; g++) m = fmaxf(m, H[g * 256 + o]);
        g_l2f[((size_t)b * 128 + s) * 256 + o] = fmaxf(m + b22[o], 0.f);
    }
}

// ---------------------------------------------------------------------------
// SA3 input build: concat(l2x, l2f) -> [B,128,259]
// ---------------------------------------------------------------------------
__global__ __launch_bounds__(256) void sa3build_kernel() {
    const int b = blockIdx.x;
    for (int e = threadIdx.x; e < 128 * 259; e += blockDim.x) {
        int n = e / 259, c = e - n * 259;
        g_sa3in[(size_t)b * 128 * 259 + e] =
            (c < 3) ? g_l2x[((size_t)b * 128 + n) * 3 + c]
                    : g_l2f[((size_t)b * 128 + n) * 256 + (c - 3)];
    }
}

// ---------------------------------------------------------------------------
// Generic GEMM + bias (+optional relu): C[b] = act(A[b] @ W + bias).
// grid (B, M/64, O/128), block 256, tile 4n x 8o, K staged in padded smem.
// which: 0 sa3in->h3a (K=259,O=256), 1 h3a->h3b (256,512),
//        2 h3b->h3c (512,1024), 3 l1f->u2 (128,128, M=512)
// ---------------------------------------------------------------------------
__global__ __launch_bounds__(256) void gemm_bias_kernel(const float* __restrict__ W,
                                                        const float* __restrict__ bias,
                                                        int K, int O, int which, int dorelu) {
    const int b = blockIdx.x, mblk = blockIdx.y, oblk = blockIdx.z;
    const float* A;
    float* C;
    int M;
    if (which == 0) { A = g_sa3in; C = g_h3a; M = 128; }
    else if (which == 1) { A = g_h3a; C = g_h3b; M = 128; }
    else if (which == 2) { A = g_h3b; C = g_h3c; M = 128; }
    else { A = g_l1f; C = g_u2; M = 512; }
    const float* Abase = A + (size_t)b * M * K;
    float* Cbase = C + (size_t)b * M * O;

    const int tid = threadIdx.x;
    const int o0 = oblk * 128 + (tid & 15) * 8;
    const int nl0 = (tid >> 4) * 4;

    __shared__ float As[64 * 33];
    float acc[4][8] = {};
    for (int kb = 0; kb < K; kb += 32) {
        const int w = min(32, K - kb);
        __syncthreads();
        for (int e = tid; e < 64 * 32; e += 256) {
            int r = e >> 5, cc = e & 31;
            As[r * 33 + cc] = (cc < w) ? Abase[(size_t)(mblk * 64 + r) * K + kb + cc] : 0.f;
        }
        __syncthreads();
        for (int c = 0; c < w; c++) {
            float4 b0 = *(const float4*)(W + (size_t)(kb + c) * O + o0);
            float4 b1 = *(const float4*)(W + (size_t)(kb + c) * O + o0 + 4);
#pragma unroll
            for (int i = 0; i < 4; i++) {
                float a = As[(nl0 + i) * 33 + c];
                acc[i][0] += a * b0.x; acc[i][1] += a * b0.y;
                acc[i][2] += a * b0.z; acc[i][3] += a * b0.w;
                acc[i][4] += a * b1.x; acc[i][5] += a * b1.y;
                acc[i][6] += a * b1.z; acc[i][7] += a * b1.w;
            }
        }
    }
    const int n0 = mblk * 64 + nl0;
#pragma unroll
    for (int i = 0; i < 4; i++)
#pragma unroll
        for (int j = 0; j < 8; j++) {
            float v = acc[i][j] + bias[o0 + j];
            if (dorelu) v = fmaxf(v, 0.f);
            Cbase[(size_t)(n0 + i) * O + o0 + j] = v;
        }
}

// ---------------------------------------------------------------------------
// Maxpool over the 128 rows of h3c -> g_g [B,1024]
// ---------------------------------------------------------------------------
__global__ __launch_bounds__(128) void maxpool_kernel() {
    const int b = blockIdx.x;
    const int o = blockIdx.y * 128 + threadIdx.x;
    float m = -1e30f;
    for (int n = 0; n < 128; n++)
        m = fmaxf(m, g_h3c[((size_t)b * 128 + n) * 1024 + o]);
    g_g[b * 1024 + o] = m;
}

// ---------------------------------------------------------------------------
// Heads: label = sigmoid(relu(g@lw1+lb1)@lw2+lb2); res = relu(g@fw1+fb1)@fw2+fb2
// ---------------------------------------------------------------------------
__global__ __launch_bounds__(256) void heads_kernel(
    const float* __restrict__ lw1, const float* __restrict__ lb1,
    const float* __restrict__ lw2, const float* __restrict__ lb2,
    const float* __restrict__ fw1, const float* __restrict__ fb1,
    const float* __restrict__ fw2, const float* __restrict__ fb2,
    const float* __restrict__ pos_mean, const float* __restrict__ pos_std,
    const float* __restrict__ rot_mean, const float* __restrict__ rot_std,
    float* __restrict__ out) {
    const int b = blockIdx.x;
    const int tid = threadIdx.x;
    __shared__ float gs[1024], h1s[256], f1s[512], res[18], lab[2];
    for (int e = tid; e < 1024; e += 256) gs[e] = g_g[b * 1024 + e];
    __syncthreads();
#pragma unroll
    for (int rep = 0; rep < 2; rep++) {
        int o = tid + rep * 256;
        float acc = fb1[o];
        for (int k = 0; k < 1024; k++) acc += gs[k] * fw1[k * 512 + o];
        f1s[o] = fmaxf(acc, 0.f);
    }
    {
        int o = tid;
        float acc = lb1[o];
        for (int k = 0; k < 1024; k++) acc += gs[k] * lw1[k * 256 + o];
        h1s[o] = fmaxf(acc, 0.f);
    }
    __syncthreads();
    if (tid < 18) {
        float acc = fb2[tid];
        for (int k = 0; k < 512; k++) acc += f1s[k] * fw2[k * 18 + tid];
        res[tid] = acc;
    } else if (tid < 20) {
        int j = tid - 18;
        float acc = lb2[j];
        for (int k = 0; k < 256; k++) acc += h1s[k] * lw2[k * 2 + j];
        lab[j] = 1.f / (1.f + expf(-acc));
    }
    __syncthreads();
    if (tid < 20) {
        float v;
        if (tid < 2) v = lab[tid];
        else if (tid < 5) { int i = tid - 2; v = res[i] * pos_std[i] + pos_mean[i]; }
        else if (tid < 11) { int i = tid - 5; v = res[3 + i] * rot_std[i] + rot_mean[i]; }
        else if (tid < 14) { int i = tid - 11; v = res[9 + i] * pos_std[i] + pos_mean[i]; }
        else { int i = tid - 14; v = res[12 + i] * rot_std[i] + rot_mean[i]; }
        out[b * 20 + tid] = v;
    }
}

// ---------------------------------------------------------------------------
extern "C" void kernel_launch(void* const* d_in, const int* in_sizes, int n_in,
                              void* d_out, int out_size) {
    (void)in_sizes; (void)n_in; (void)out_size;
    const float* pts = (const float*)d_in[0];
    const float* w10 = (const float*)d_in[1];  const float* b10 = (const float*)d_in[2];
    const float* w11 = (const float*)d_in[3];  const float* b11 = (const float*)d_in[4];
    const float* w12 = (const float*)d_in[5];  const float* b12 = (const float*)d_in[6];
    const float* w20 = (const float*)d_in[7];  const float* b20 = (const float*)d_in[8];
    const float* w21 = (const float*)d_in[9];  const float* b21 = (const float*)d_in[10];
    const float* w22 = (const float*)d_in[11]; const float* b22 = (const float*)d_in[12];
    const float* w30 = (const float*)d_in[13]; const float* b30 = (const float*)d_in[14];
    const float* w31 = (const float*)d_in[15]; const float* b31 = (const float*)d_in[16];
    const float* w32 = (const float*)d_in[17]; const float* b32 = (const float*)d_in[18];
    const float* lw1 = (const float*)d_in[19]; const float* lb1 = (const float*)d_in[20];
    const float* lw2 = (const float*)d_in[21]; const float* lb2 = (const float*)d_in[22];
    const float* fw1 = (const float*)d_in[23]; const float* fb1 = (const float*)d_in[24];
    const float* fw2 = (const float*)d_in[25]; const float* fb2 = (const float*)d_in[26];
    const float* pos_mean = (const float*)d_in[27];
    const float* pos_std  = (const float*)d_in[28];
    const float* rot_mean = (const float*)d_in[29];
    const float* rot_std  = (const float*)d_in[30];
    float* out = (float*)d_out;

    cudaFuncSetAttribute(fps_kernel, cudaFuncAttributeMaxDynamicSharedMemorySize,
                         NPTS * 3 * 4 + 512);

    fps_kernel<<<BATCH, 1024, NPTS * 3 * 4 + 320>>>(pts, NPTS, 512, 0);
    sa1_kernel<<<dim3(512, BATCH), 128>>>(pts, w10, b10, w11, b11, w12, b12);
    fps_kernel<<<BATCH, 512, 512 * 3 * 4 + 320>>>(pts, 512, 128, 1);
    // U2 = l1f @ w20[3:,:] + b20   (per-l1-point feature projection, shared by groups)
    gemm_bias_kernel<<<dim3(BATCH, 8, 1), 256>>>(w20 + 3 * 128, b20, 128, 128, 3, 0);
    sa2_kernel<<<dim3(128, BATCH), 256>>>(w20, w21, b21, w22, b22);
    sa3build_kernel<<<BATCH, 256>>>();
    gemm_bias_kernel<<<dim3(BATCH, 2, 2), 256>>>(w30, b30, 259, 256, 0, 1);
    gemm_bias_kernel<<<dim3(BATCH, 2, 4), 256>>>(w31, b31, 256, 512, 1, 1);
    gemm_bias_kernel<<<dim3(BATCH, 2, 8), 256>>>(w32, b32, 512, 1024, 2, 1);
    maxpool_kernel<<<dim3(BATCH, 8), 128>>>();
    heads_kernel<<<BATCH, 256>>>(lw1, lb1, lw2, lb2, fw1, fb1, fw2, fb2,
                                 pos_mean, pos_std, rot_mean, rot_std, out);
}

// round 5
// speedup vs baseline: 1.7188x; 1.0960x over previous
#include <cuda_runtime.h>
#include <cuda_bf16.h>
#include <math.h>

// ---------------------------------------------------------------------------
// PointNet++ grasp net forward. B=16, N=4096.
// FPS1 -> SA1 -> FPS2 -> U2-precompute -> SA2 -> SA3(GEMMs+max) -> heads
// ---------------------------------------------------------------------------

#define BATCH 16
#define NPTS 4096

// exact f32 thresholds as JAX sees them (python double radius*radius -> f32)
#define R2A ((float)(0.2 * 0.2))
#define R2B ((float)(0.4 * 0.4))

// ------------------------- device scratch (static) -------------------------
__device__ __align__(16) float g_l1x[BATCH * 512 * 3];
__device__ __align__(16) float g_l1f[BATCH * 512 * 128];
__device__ __align__(16) float g_u2[BATCH * 512 * 128];   // l1f @ w20[3:] + b20
__device__ __align__(16) float g_l2x[BATCH * 128 * 3];
__device__ __align__(16) float g_l2f[BATCH * 128 * 256];
__device__ __align__(16) float g_sa3in[BATCH * 128 * 259];
__device__ __align__(16) float g_h3a[BATCH * 128 * 256];
__device__ __align__(16) float g_h3b[BATCH * 128 * 512];
__device__ __align__(16) float g_h3c[BATCH * 128 * 1024];
__device__ __align__(16) float g_g[BATCH * 1024];

// ---------------------------------------------------------------------------
// FPS: one block per batch. phase 0: src = input points (n=4096) -> g_l1x
//      phase 1: src = g_l1x (n=512) -> g_l2x
// ONE barrier per iteration: per-warp candidates are double-buffered by
// iteration parity; after the barrier every warp xor-reduces the 32
// candidates so all threads compute `far` locally (identical comparisons ->
// identical result). Exact jnp semantics preserved (dist init 1e10,
// first-index tie-break, no FMA contraction in distances).
// ---------------------------------------------------------------------------
extern __shared__ float fps_sm[];

__global__ __launch_bounds__(1024) void fps_kernel(const float* __restrict__ pts_in,
                                                   int n, int S, int phase) {
    const int b = blockIdx.x;
    const float* p = (phase == 0 ? pts_in : g_l1x) + (size_t)b * n * 3;
    float* outxyz = (phase == 0 ? g_l1x : g_l2x);

    const int tid = threadIdx.x, BT = blockDim.x;
    float* sp = fps_sm;                  // n*3 point cache
    float* rv = fps_sm + n * 3;          // 2 x 32 candidate vals (parity)
    int* ri = (int*)(rv + 64);           // 2 x 32 candidate idxs

    for (int e = tid; e < n * 3; e += BT) sp[e] = p[e];

    const int PT = n / BT;  // 4 (phase 0) or 1 (phase 1)
    float px[4], py[4], pz[4], dd[4];
#pragma unroll
    for (int k = 0; k < 4; k++) {
        if (k < PT) {
            int i = tid + k * BT;
            px[k] = p[i * 3 + 0];
            py[k] = p[i * 3 + 1];
            pz[k] = p[i * 3 + 2];
            dd[k] = 1e10f;
        }
    }
    __syncthreads();

    const int lane = tid & 31, wid = tid >> 5, nw = BT >> 5;
    const int lsel = lane & (nw - 1);  // candidate slot this lane reads
    int far = 0;

    for (int s = 0; s < S; s++) {
        const float fx = sp[far * 3 + 0], fy = sp[far * 3 + 1], fz = sp[far * 3 + 2];
        if (tid == 0) {
            float* o = outxyz + ((size_t)b * S + s) * 3;
            o[0] = fx; o[1] = fy; o[2] = fz;
        }
        float bv = -1.0f;
        int bi = 0x7fffffff;
#pragma unroll
        for (int k = 0; k < 4; k++) {
            if (k < PT) {
                float dx = __fsub_rn(px[k], fx);
                float dy = __fsub_rn(py[k], fy);
                float dz = __fsub_rn(pz[k], fz);
                float d = __fadd_rn(__fadd_rn(__fmul_rn(dx, dx), __fmul_rn(dy, dy)),
                                    __fmul_rn(dz, dz));
                float ndv = fminf(dd[k], d);
                dd[k] = ndv;
                if (ndv > bv) { bv = ndv; bi = tid + k * BT; }  // ascending k keeps min idx
            }
        }
        // warp reduce: max val, min idx on tie
#pragma unroll
        for (int off = 16; off > 0; off >>= 1) {
            float ov = __shfl_down_sync(0xffffffffu, bv, off);
            int oi = __shfl_down_sync(0xffffffffu, bi, off);
            if (ov > bv || (ov == bv && oi < bi)) { bv = ov; bi = oi; }
        }
        const int po = (s & 1) * 32;
        if (lane == 0) { rv[po + wid] = bv; ri[po + wid] = bi; }
        __syncthreads();
        // every warp reduces the candidate set (nw<=32); all lanes converge
        float v = rv[po + lsel];
        int i2 = ri[po + lsel];
#pragma unroll
        for (int off = 16; off > 0; off >>= 1) {
            float ov = __shfl_xor_sync(0xffffffffu, v, off);
            int oi = __shfl_xor_sync(0xffffffffu, i2, off);
            if (ov > v || (ov == v && oi < i2)) { v = ov; i2 = oi; }
        }
        far = i2;
    }
}

// ---------------------------------------------------------------------------
// SA1: TWO groups per block (256 threads). Ball query (r=0.2, ns=32) over
// 4096 pts for both centers from one point load; 64-row (2x32) MLP
// 3->64->64->128 as dense row-independent GEMM tiles; per-half maxpool.
// ---------------------------------------------------------------------------
#define P1 68  // padded pitch for 64-wide smem rows

__global__ __launch_bounds__(256) void sa1_kernel(
    const float* __restrict__ pts,
    const float* __restrict__ w10, const float* __restrict__ b10,
    const float* __restrict__ w11, const float* __restrict__ b11,
    const float* __restrict__ w12, const float* __restrict__ b12) {
    const int sp2 = blockIdx.x;  // group pair: groups 2*sp2, 2*sp2+1
    const int b = blockIdx.y;
    const int tid = threadIdx.x;
    const float* p = pts + (size_t)b * NPTS * 3;

    __shared__ unsigned smaskA[128], smaskB[128];
    __shared__ int sel[64];
    __shared__ float ctr[6];
    __shared__ float Ax[64 * 3];
    __shared__ float H1[64 * P1];  // later reused as Pm[16][128]
    __shared__ float H2[64 * P1];

    if (tid < 6) ctr[tid] = g_l1x[((size_t)b * 512 + sp2 * 2) * 3 + tid];
    __syncthreads();
    const float cax = ctr[0], cay = ctr[1], caz = ctr[2];
    const float cbx = ctr[3], cby = ctr[4], cbz = ctr[5];

    const int lane = tid & 31, wid = tid >> 5;
    for (int w = wid; w < 128; w += 8) {
        int j = w * 32 + lane;
        float x = p[j * 3 + 0], y = p[j * 3 + 1], z = p[j * 3 + 2];
        float dax = __fsub_rn(cax, x), day = __fsub_rn(cay, y), daz = __fsub_rn(caz, z);
        float da = __fadd_rn(__fadd_rn(__fmul_rn(dax, dax), __fmul_rn(day, day)),
                             __fmul_rn(daz, daz));
        float dbx = __fsub_rn(cbx, x), dby = __fsub_rn(cby, y), dbz = __fsub_rn(cbz, z);
        float db = __fadd_rn(__fadd_rn(__fmul_rn(dbx, dbx), __fmul_rn(dby, dby)),
                             __fmul_rn(dbz, dbz));
        unsigned mA = __ballot_sync(0xffffffffu, !(da > R2A));
        unsigned mB = __ballot_sync(0xffffffffu, !(db > R2A));
        if (lane == 0) { smaskA[w] = mA; smaskB[w] = mB; }
    }
    __syncthreads();
    if (tid == 0) {
        int cnt = 0;
        for (int w = 0; w < 128 && cnt < 32; w++) {
            unsigned m = smaskA[w];
            while (m && cnt < 32) {
                int t = __ffs(m) - 1;
                m &= m - 1;
                sel[cnt++] = w * 32 + t;
            }
        }
        int c0 = sel[0];
        for (int j = cnt; j < 32; j++) sel[j] = c0;
    } else if (tid == 128) {
        int cnt = 0;
        for (int w = 0; w < 128 && cnt < 32; w++) {
            unsigned m = smaskB[w];
            while (m && cnt < 32) {
                int t = __ffs(m) - 1;
                m &= m - 1;
                sel[32 + cnt++] = w * 32 + t;
            }
        }
        int c0 = sel[32];
        for (int j = cnt; j < 32; j++) sel[32 + j] = c0;
    }
    __syncthreads();
    if (tid < 192) {
        int n = tid / 3, c = tid - n * 3;
        float cc = (n < 32) ? ctr[c] : ctr[3 + c];
        Ax[n * 3 + c] = p[sel[n] * 3 + c] - cc;
    }
    __syncthreads();

    // L1: 3 -> 64 for 64 rows (16 outputs/thread)
#pragma unroll
    for (int r = 0; r < 16; r++) {
        int lin = r * 256 + tid;
        int n = lin >> 6, o = lin & 63;
        float a = b10[o] + Ax[n * 3 + 0] * w10[o] + Ax[n * 3 + 1] * w10[64 + o] +
                  Ax[n * 3 + 2] * w10[128 + o];
        H1[n * P1 + o] = fmaxf(a, 0.f);
    }
    __syncthreads();

    // L2: 64 -> 64 over 64 rows (tile 4n x 4o)
    {
        const int o0 = (tid & 15) * 4, n0 = (tid >> 4) * 4;
        float acc[4][4] = {};
        for (int c = 0; c < 64; c++) {
            float4 bvv = *(const float4*)(w11 + c * 64 + o0);
#pragma unroll
            for (int i = 0; i < 4; i++) {
                float a = H1[(n0 + i) * P1 + c];
                acc[i][0] += a * bvv.x; acc[i][1] += a * bvv.y;
                acc[i][2] += a * bvv.z; acc[i][3] += a * bvv.w;
            }
        }
        __syncthreads();  // H1 reads done before Pm (=H1) overwrite in L3
#pragma unroll
        for (int i = 0; i < 4; i++)
#pragma unroll
            for (int j = 0; j < 4; j++)
                H2[(n0 + i) * P1 + o0 + j] = fmaxf(acc[i][j] + b11[o0 + j], 0.f);
    }
    __syncthreads();

    // L3: 64 -> 128 with fused partial maxpool (tile 4n x 8o); Pm reuses H1
    float* Pm = H1;  // [16][128]
    {
        const int o0 = (tid & 15) * 8, ng = tid >> 4, n0 = ng * 4;
        float acc[4][8] = {};
        for (int c = 0; c < 64; c++) {
            float4 b0 = *(const float4*)(w12 + c * 128 + o0);
            float4 b1 = *(const float4*)(w12 + c * 128 + o0 + 4);
#pragma unroll
            for (int i = 0; i < 4; i++) {
                float a = H2[(n0 + i) * P1 + c];
                acc[i][0] += a * b0.x; acc[i][1] += a * b0.y;
                acc[i][2] += a * b0.z; acc[i][3] += a * b0.w;
                acc[i][4] += a * b1.x; acc[i][5] += a * b1.y;
                acc[i][6] += a * b1.z; acc[i][7] += a * b1.w;
            }
        }
#pragma unroll
        for (int j = 0; j < 8; j++) {
            float m = acc[0][j];
#pragma unroll
            for (int i = 1; i < 4; i++) m = fmaxf(m, acc[i][j]);
            Pm[ng * 128 + o0 + j] = m;
        }
    }
    __syncthreads();
    {
        int h = tid >> 7, o = tid & 127;  // half (group) and channel
        float m = Pm[(h * 8) * 128 + o];
#pragma unroll
        for (int g = 1; g < 8; g++) m = fmaxf(m, Pm[(h * 8 + g) * 128 + o]);
        g_l1f[((size_t)b * 512 + sp2 * 2 + h) * 128 + o] = fmaxf(m + b12[o], 0.f);
    }
}

// ---------------------------------------------------------------------------
// SA2: per (b,s): ball query (r=0.4, ns=64) over 512 pts.
// L1 via precomputed U2 gather: h1 = relu(dxyz @ w20[0:3] + U2[sel])
// then 128->128, 128->256 + maxpool. Block = 256 threads.
// ---------------------------------------------------------------------------
#define P2 132  // padded pitch (mod 4 == 0) for 128-wide smem rows

__global__ __launch_bounds__(256) void sa2_kernel(
    const float* __restrict__ w20,
    const float* __restrict__ w21, const float* __restrict__ b21,
    const float* __restrict__ w22, const float* __restrict__ b22) {
    const int s = blockIdx.x, b = blockIdx.y;
    const int tid = threadIdx.x;
    const float* px = g_l1x + (size_t)b * 512 * 3;

    __shared__ __align__(16) float H[64 * P2];  // H1 -> H2 -> partial maxes [8][256]
    __shared__ unsigned smask[16];
    __shared__ int sel[64];
    __shared__ float ctr[3];
    __shared__ float dx3[64 * 3];

    if (tid < 3) ctr[tid] = g_l2x[((size_t)b * 128 + s) * 3 + tid];
    __syncthreads();
    const float cx = ctr[0], cy = ctr[1], cz = ctr[2];

    const int lane = tid & 31, wid = tid >> 5;
    for (int w = wid; w < 16; w += 8) {
        int j = w * 32 + lane;
        float dx = __fsub_rn(cx, px[j * 3 + 0]);
        float dy = __fsub_rn(cy, px[j * 3 + 1]);
        float dz = __fsub_rn(cz, px[j * 3 + 2]);
        float d = __fadd_rn(__fadd_rn(__fmul_rn(dx, dx), __fmul_rn(dy, dy)),
                            __fmul_rn(dz, dz));
        unsigned m = __ballot_sync(0xffffffffu, !(d > R2B));
        if (lane == 0) smask[w] = m;
    }
    __syncthreads();
    if (tid == 0) {
        int cnt = 0;
        for (int w = 0; w < 16 && cnt < 64; w++) {
            unsigned m = smask[w];
            while (m && cnt < 64) {
                int t = __ffs(m) - 1;
                m &= m - 1;
                sel[cnt++] = w * 32 + t;
            }
        }
        int c0 = sel[0];
        for (int j = cnt; j < 64; j++) sel[j] = c0;
    }
    __syncthreads();
    if (tid < 192) {
        int n = tid / 3, c = tid - n * 3;
        float cc = (c == 0) ? cx : ((c == 1) ? cy : cz);
        dx3[tid] = px[sel[n] * 3 + c] - cc;
    }
    __syncthreads();

    // L1: gather U2 + xyz contribution, relu. 8n x 4o per thread.
    {
        const int o0 = (tid & 31) * 4, n0 = (tid >> 5) * 8;
        float4 wxv = *(const float4*)(w20 + o0);
        float4 wyv = *(const float4*)(w20 + 128 + o0);
        float4 wzv = *(const float4*)(w20 + 256 + o0);
#pragma unroll
        for (int i = 0; i < 8; i++) {
            int n = n0 + i;
            float ddx = dx3[n * 3 + 0], ddy = dx3[n * 3 + 1], ddz = dx3[n * 3 + 2];
            float4 u = *(const float4*)(g_u2 + ((size_t)b * 512 + sel[n]) * 128 + o0);
            float4 r;
            r.x = fmaxf(u.x + ddx * wxv.x + ddy * wyv.x + ddz * wzv.x, 0.f);
            r.y = fmaxf(u.y + ddx * wxv.y + ddy * wyv.y + ddz * wzv.y, 0.f);
            r.z = fmaxf(u.z + ddx * wxv.z + ddy * wyv.z + ddz * wzv.z, 0.f);
            r.w = fmaxf(u.w + ddx * wxv.w + ddy * wyv.w + ddz * wzv.w, 0.f);
            *(float4*)(H + n * P2 + o0) = r;
        }
    }
    __syncthreads();

    // L2: 128 -> 128 (tile 4n x 8o), accumulate in regs, then overwrite H
    {
        const int o0 = (tid & 15) * 8, n0 = (tid >> 4) * 4;
        float acc[4][8] = {};
        for (int c = 0; c < 128; c++) {
            float4 b0 = *(const float4*)(w21 + c * 128 + o0);
            float4 b1 = *(const float4*)(w21 + c * 128 + o0 + 4);
#pragma unroll
            for (int i = 0; i < 4; i++) {
                float a = H[(n0 + i) * P2 + c];
                acc[i][0] += a * b0.x; acc[i][1] += a * b0.y;
                acc[i][2] += a * b0.z; acc[i][3] += a * b0.w;
                acc[i][4] += a * b1.x; acc[i][5] += a * b1.y;
                acc[i][6] += a * b1.z; acc[i][7] += a * b1.w;
            }
        }
        __syncthreads();
#pragma unroll
        for (int i = 0; i < 4; i++)
#pragma unroll
            for (int j = 0; j < 8; j++)
                H[(n0 + i) * P2 + o0 + j] = fmaxf(acc[i][j] + b21[o0 + j], 0.f);
    }
    __syncthreads();

    // L3: 128 -> 256 with fused partial maxpool (tile 8n x 8o)
    {
        const int o0 = (tid & 31) * 8, ng = tid >> 5, n0 = ng * 8;
        float acc[8][8] = {};
        for (int c = 0; c < 128; c++) {
            float4 b0 = *(const float4*)(w22 + c * 256 + o0);
            float4 b1 = *(const float4*)(w22 + c * 256 + o0 + 4);
#pragma unroll
            for (int i = 0; i < 8; i++) {
                float a = H[(n0 + i) * P2 + c];
                acc[i][0] += a * b0.x; acc[i][1] += a * b0.y;
                acc[i][2] += a * b0.z; acc[i][3] += a * b0.w;
                acc[i][4] += a * b1.x; acc[i][5] += a * b1.y;
                acc[i][6] += a * b1.z; acc[i][7] += a * b1.w;
            }
        }
        __syncthreads();
#pragma unroll
        for (int j = 0; j < 8; j++) {
            float m = acc[0][j];
#pragma unroll
            for (int i = 1; i < 8; i++) m = fmaxf(m, acc[i][j]);
            H[ng * 256 + o0 + j] = m;  // reuse H as Pm[8][256]
        }
    }
    __syncthreads();
    {
        int o = tid;
        float m = H[o];
#pragma unroll
        for (int g = 1; g < 8; g++) m = fmaxf(m, H[g * 256 + o]);
        g_l2f[((size_t)b * 128 + s) * 256 + o] = fmaxf(m + b22[o], 0.f);
    }
}

// ---------------------------------------------------------------------------
// SA3 input build: concat(l2x, l2f) -> [B,128,259]
// ---------------------------------------------------------------------------
__global__ __launch_bounds__(256) void sa3build_kernel() {
    const int b = blockIdx.x;
    for (int e = threadIdx.x; e < 128 * 259; e += blockDim.x) {
        int n = e / 259, c = e - n * 259;
        g_sa3in[(size_t)b * 128 * 259 + e] =
            (c < 3) ? g_l2x[((size_t)b * 128 + n) * 3 + c]
                    : g_l2f[((size_t)b * 128 + n) * 256 + (c - 3)];
    }
}

// ---------------------------------------------------------------------------
// Generic GEMM + bias (+optional relu), batch flattened into M:
// C = act(A @ W + bias), A [M_total, K] row-major contiguous across batch.
// grid (M_total/64, O/64), block 256, tile 4n x 4o.
// which: 0 sa3in->h3a (K=259,O=256), 1 h3a->h3b (256,512),
//        2 h3b->h3c (512,1024), 3 l1f->u2 (128,128)
// ---------------------------------------------------------------------------
__global__ __launch_bounds__(256) void gemm_bias_kernel(const float* __restrict__ W,
                                                        const float* __restrict__ bias,
                                                        int K, int O, int which, int dorelu) {
    const int mblk = blockIdx.x, oblk = blockIdx.y;
    const float* A;
    float* C;
    if (which == 0) { A = g_sa3in; C = g_h3a; }
    else if (which == 1) { A = g_h3a; C = g_h3b; }
    else if (which == 2) { A = g_h3b; C = g_h3c; }
    else { A = g_l1f; C = g_u2; }

    const int tid = threadIdx.x;
    const int o0 = oblk * 64 + (tid & 15) * 4;
    const int nl0 = (tid >> 4) * 4;
    const int row0 = mblk * 64;

    __shared__ float As[64 * 33];
    float acc[4][4] = {};
    for (int kb = 0; kb < K; kb += 32) {
        const int w = min(32, K - kb);
        __syncthreads();
        for (int e = tid; e < 64 * 32; e += 256) {
            int r = e >> 5, cc = e & 31;
            As[r * 33 + cc] = (cc < w) ? A[(size_t)(row0 + r) * K + kb + cc] : 0.f;
        }
        __syncthreads();
        for (int c = 0; c < w; c++) {
            float4 bvv = *(const float4*)(W + (size_t)(kb + c) * O + o0);
#pragma unroll
            for (int i = 0; i < 4; i++) {
                float a = As[(nl0 + i) * 33 + c];
                acc[i][0] += a * bvv.x; acc[i][1] += a * bvv.y;
                acc[i][2] += a * bvv.z; acc[i][3] += a * bvv.w;
            }
        }
    }
#pragma unroll
    for (int i = 0; i < 4; i++)
#pragma unroll
        for (int j = 0; j < 4; j++) {
            float v = acc[i][j] + bias[o0 + j];
            if (dorelu) v = fmaxf(v, 0.f);
            C[(size_t)(row0 + nl0 + i) * O + o0 + j] = v;
        }
}

// ---------------------------------------------------------------------------
// Maxpool over the 128 rows of h3c -> g_g [B,1024]
// ---------------------------------------------------------------------------
__global__ __launch_bounds__(128) void maxpool_kernel() {
    const int b = blockIdx.x;
    const int o = blockIdx.y * 128 + threadIdx.x;
    float m = -1e30f;
    for (int n = 0; n < 128; n++)
        m = fmaxf(m, g_h3c[((size_t)b * 128 + n) * 1024 + o]);
    g_g[b * 1024 + o] = m;
}

// ---------------------------------------------------------------------------
// Heads: label = sigmoid(relu(g@lw1+lb1)@lw2+lb2); res = relu(g@fw1+fb1)@fw2+fb2
// ---------------------------------------------------------------------------
__global__ __launch_bounds__(256) void heads_kernel(
    const float* __restrict__ lw1, const float* __restrict__ lb1,
    const float* __restrict__ lw2, const float* __restrict__ lb2,
    const float* __restrict__ fw1, const float* __restrict__ fb1,
    const float* __restrict__ fw2, const float* __restrict__ fb2,
    const float* __restrict__ pos_mean, const float* __restrict__ pos_std,
    const float* __restrict__ rot_mean, const float* __restrict__ rot_std,
    float* __restrict__ out) {
    const int b = blockIdx.x;
    const int tid = threadIdx.x;
    __shared__ float gs[1024], h1s[256], f1s[512], res[18], lab[2];
    for (int e = tid; e < 1024; e += 256) gs[e] = g_g[b * 1024 + e];
    __syncthreads();
#pragma unroll
    for (int rep = 0; rep < 2; rep++) {
        int o = tid + rep * 256;
        float acc = fb1[o];
        for (int k = 0; k < 1024; k++) acc += gs[k] * fw1[k * 512 + o];
        f1s[o] = fmaxf(acc, 0.f);
    }
    {
        int o = tid;
        float acc = lb1[o];
        for (int k = 0; k < 1024; k++) acc += gs[k] * lw1[k * 256 + o];
        h1s[o] = fmaxf(acc, 0.f);
    }
    __syncthreads();
    if (tid < 18) {
        float acc = fb2[tid];
        for (int k = 0; k < 512; k++) acc += f1s[k] * fw2[k * 18 + tid];
        res[tid] = acc;
    } else if (tid < 20) {
        int j = tid - 18;
        float acc = lb2[j];
        for (int k = 0; k < 256; k++) acc += h1s[k] * lw2[k * 2 + j];
        lab[j] = 1.f / (1.f + expf(-acc));
    }
    __syncthreads();
    if (tid < 20) {
        float v;
        if (tid < 2) v = lab[tid];
        else if (tid < 5) { int i = tid - 2; v = res[i] * pos_std[i] + pos_mean[i]; }
        else if (tid < 11) { int i = tid - 5; v = res[3 + i] * rot_std[i] + rot_mean[i]; }
        else if (tid < 14) { int i = tid - 11; v = res[9 + i] * pos_std[i] + pos_mean[i]; }
        else { int i = tid - 14; v = res[12 + i] * rot_std[i] + rot_mean[i]; }
        out[b * 20 + tid] = v;
    }
}

// ---------------------------------------------------------------------------
extern "C" void kernel_launch(void* const* d_in, const int* in_sizes, int n_in,
                              void* d_out, int out_size) {
    (void)in_sizes; (void)n_in; (void)out_size;
    const float* pts = (const float*)d_in[0];
    const float* w10 = (const float*)d_in[1];  const float* b10 = (const float*)d_in[2];
    const float* w11 = (const float*)d_in[3];  const float* b11 = (const float*)d_in[4];
    const float* w12 = (const float*)d_in[5];  const float* b12 = (const float*)d_in[6];
    const float* w20 = (const float*)d_in[7];  const float* b20 = (const float*)d_in[8];
    const float* w21 = (const float*)d_in[9];  const float* b21 = (const float*)d_in[10];
    const float* w22 = (const float*)d_in[11]; const float* b22 = (const float*)d_in[12];
    const float* w30 = (const float*)d_in[13]; const float* b30 = (const float*)d_in[14];
    const float* w31 = (const float*)d_in[15]; const float* b31 = (const float*)d_in[16];
    const float* w32 = (const float*)d_in[17]; const float* b32 = (const float*)d_in[18];
    const float* lw1 = (const float*)d_in[19]; const float* lb1 = (const float*)d_in[20];
    const float* lw2 = (const float*)d_in[21]; const float* lb2 = (const float*)d_in[22];
    const float* fw1 = (const float*)d_in[23]; const float* fb1 = (const float*)d_in[24];
    const float* fw2 = (const float*)d_in[25]; const float* fb2 = (const float*)d_in[26];
    const float* pos_mean = (const float*)d_in[27];
    const float* pos_std  = (const float*)d_in[28];
    const float* rot_mean = (const float*)d_in[29];
    const float* rot_std  = (const float*)d_in[30];
    float* out = (float*)d_out;

    cudaFuncSetAttribute(fps_kernel, cudaFuncAttributeMaxDynamicSharedMemorySize,
                         NPTS * 3 * 4 + 1024);

    fps_kernel<<<BATCH, 1024, NPTS * 3 * 4 + 768>>>(pts, NPTS, 512, 0);
    sa1_kernel<<<dim3(256, BATCH), 256>>>(pts, w10, b10, w11, b11, w12, b12);
    fps_kernel<<<BATCH, 512, 512 * 3 * 4 + 768>>>(pts, 512, 128, 1);
    // U2 = l1f @ w20[3:,:] + b20   (per-l1-point feature projection, shared by groups)
    gemm_bias_kernel<<<dim3(BATCH * 512 / 64, 2), 256>>>(w20 + 3 * 128, b20, 128, 128, 3, 0);
    sa2_kernel<<<dim3(128, BATCH), 256>>>(w20, w21, b21, w22, b22);
    sa3build_kernel<<<BATCH, 256>>>();
    gemm_bias_kernel<<<dim3(BATCH * 128 / 64, 4), 256>>>(w30, b30, 259, 256, 0, 1);
    gemm_bias_kernel<<<dim3(BATCH * 128 / 64, 8), 256>>>(w31, b31, 256, 512, 1, 1);
    gemm_bias_kernel<<<dim3(BATCH * 128 / 64, 16), 256>>>(w32, b32, 512, 1024, 2, 1);
    maxpool_kernel<<<dim3(BATCH, 8), 128>>>();
    heads_kernel<<<BATCH, 256>>>(lw1, lb1, lw2, lb2, fw1, fb1, fw2, fb2,
                                 pos_mean, pos_std, rot_mean, rot_std, out);
}

// round 7
// speedup vs baseline: 2.0430x; 1.1886x over previous
#include <cuda_runtime.h>
#include <cuda_bf16.h>
#include <stdint.h>
#include <math.h>

// ---------------------------------------------------------------------------
// PointNet++ grasp net forward. B=16, N=4096.
// FPS1 -> SA1 -> FPS2 -> U2-precompute -> SA2 -> SA3(GEMMs+max) -> heads
// SA1/SA2 mid layers run on tensor cores (tf32 mma.sync, fp32 accumulate).
// ---------------------------------------------------------------------------

#define BATCH 16
#define NPTS 4096

// exact f32 thresholds as JAX sees them (python double radius*radius -> f32)
#define R2A ((float)(0.2 * 0.2))
#define R2B ((float)(0.4 * 0.4))

// ------------------------- device scratch (static) -------------------------
__device__ __align__(16) float g_l1x[BATCH * 512 * 3];
__device__ __align__(16) float g_l1f[BATCH * 512 * 128];
__device__ __align__(16) float g_u2[BATCH * 512 * 128];   // l1f @ w20[3:] + b20
__device__ __align__(16) float g_l2x[BATCH * 128 * 3];
__device__ __align__(16) float g_l2f[BATCH * 128 * 256];
__device__ __align__(16) float g_sa3in[BATCH * 128 * 259];
__device__ __align__(16) float g_h3a[BATCH * 128 * 256];
__device__ __align__(16) float g_h3b[BATCH * 128 * 512];
__device__ __align__(16) float g_h3c[BATCH * 128 * 1024];
__device__ __align__(16) float g_g[BATCH * 1024];

// ------------------------- tf32 mma helpers --------------------------------
__device__ __forceinline__ uint32_t f2tf(float v) {
    uint32_t r;
    asm("cvt.rna.tf32.f32 %0, %1;" : "=r"(r) : "f"(v));
    return r;
}
__device__ __forceinline__ void mma_tf32(float* d, uint32_t a0, uint32_t a1,
                                         uint32_t a2, uint32_t a3,
                                         uint32_t b0, uint32_t b1) {
    asm volatile(
        "mma.sync.aligned.m16n8k8.row.col.f32.tf32.tf32.f32 "
        "{%0,%1,%2,%3}, {%4,%5,%6,%7}, {%8,%9}, {%0,%1,%2,%3};"
        : "+f"(d[0]), "+f"(d[1]), "+f"(d[2]), "+f"(d[3])
        : "r"(a0), "r"(a1), "r"(a2), "r"(a3), "r"(b0), "r"(b1));
}

// ---------------------------------------------------------------------------
// FPS: one block per batch. ONE barrier per iteration (parity-double-buffered
// candidates; every warp reduces them so all threads compute `far` locally).
// Exact jnp semantics: dist init 1e10, first-index tie-break, no FMA fusion.
// ---------------------------------------------------------------------------
extern __shared__ float fps_sm[];

__global__ __launch_bounds__(1024) void fps_kernel(const float* __restrict__ pts_in,
                                                   int n, int S, int phase) {
    const int b = blockIdx.x;
    const float* p = (phase == 0 ? pts_in : g_l1x) + (size_t)b * n * 3;
    float* outxyz = (phase == 0 ? g_l1x : g_l2x);

    const int tid = threadIdx.x, BT = blockDim.x;
    float* sp = fps_sm;
    float* rv = fps_sm + n * 3;
    int* ri = (int*)(rv + 64);

    for (int e = tid; e < n * 3; e += BT) sp[e] = p[e];

    const int PT = n / BT;
    float px[4], py[4], pz[4], dd[4];
#pragma unroll
    for (int k = 0; k < 4; k++) {
        if (k < PT) {
            int i = tid + k * BT;
            px[k] = p[i * 3 + 0];
            py[k] = p[i * 3 + 1];
            pz[k] = p[i * 3 + 2];
            dd[k] = 1e10f;
        }
    }
    __syncthreads();

    const int lane = tid & 31, wid = tid >> 5, nw = BT >> 5;
    const int lsel = lane & (nw - 1);
    int far = 0;

    for (int s = 0; s < S; s++) {
        const float fx = sp[far * 3 + 0], fy = sp[far * 3 + 1], fz = sp[far * 3 + 2];
        if (tid == 0) {
            float* o = outxyz + ((size_t)b * S + s) * 3;
            o[0] = fx; o[1] = fy; o[2] = fz;
        }
        float bv = -1.0f;
        int bi = 0x7fffffff;
#pragma unroll
        for (int k = 0; k < 4; k++) {
            if (k < PT) {
                float dx = __fsub_rn(px[k], fx);
                float dy = __fsub_rn(py[k], fy);
                float dz = __fsub_rn(pz[k], fz);
                float d = __fadd_rn(__fadd_rn(__fmul_rn(dx, dx), __fmul_rn(dy, dy)),
                                    __fmul_rn(dz, dz));
                float ndv = fminf(dd[k], d);
                dd[k] = ndv;
                if (ndv > bv) { bv = ndv; bi = tid + k * BT; }
            }
        }
#pragma unroll
        for (int off = 16; off > 0; off >>= 1) {
            float ov = __shfl_down_sync(0xffffffffu, bv, off);
            int oi = __shfl_down_sync(0xffffffffu, bi, off);
            if (ov > bv || (ov == bv && oi < bi)) { bv = ov; bi = oi; }
        }
        const int po = (s & 1) * 32;
        if (lane == 0) { rv[po + wid] = bv; ri[po + wid] = bi; }
        __syncthreads();
        float v = rv[po + lsel];
        int i2 = ri[po + lsel];
#pragma unroll
        for (int off = 16; off > 0; off >>= 1) {
            float ov = __shfl_xor_sync(0xffffffffu, v, off);
            int oi = __shfl_xor_sync(0xffffffffu, i2, off);
            if (ov > v || (ov == v && oi < i2)) { v = ov; i2 = oi; }
        }
        far = i2;
    }
}

// ---------------------------------------------------------------------------
// SA1: TWO groups per block (256 thr). Ball query r=0.2 ns=32 over 4096 pts;
// L1 (3->64) scalar; L2 (64->64) and L3 (64->128, fused maxpool) on tf32 mma.
// 64 rows = 4 m16 tiles; 8 warps = (4 m-tiles) x (2 n-halves).
// ---------------------------------------------------------------------------
#define P1 68  // padded pitch for 64-wide smem rows

__global__ __launch_bounds__(256) void sa1_kernel(
    const float* __restrict__ pts,
    const float* __restrict__ w10, const float* __restrict__ b10,
    const float* __restrict__ w11, const float* __restrict__ b11,
    const float* __restrict__ w12, const float* __restrict__ b12) {
    const int sp2 = blockIdx.x;
    const int b = blockIdx.y;
    const int tid = threadIdx.x;
    const float* p = pts + (size_t)b * NPTS * 3;

    __shared__ unsigned smaskA[128], smaskB[128];
    __shared__ int sel[64];
    __shared__ float ctr[6];
    __shared__ float Ax[64 * 3];
    __shared__ float H1[64 * P1];  // reused as Pm[4][128] after L2 reads
    __shared__ float H2[64 * P1];

    if (tid < 6) ctr[tid] = g_l1x[((size_t)b * 512 + sp2 * 2) * 3 + tid];
    __syncthreads();
    const float cax = ctr[0], cay = ctr[1], caz = ctr[2];
    const float cbx = ctr[3], cby = ctr[4], cbz = ctr[5];

    const int lane = tid & 31, warp = tid >> 5;
    for (int w = warp; w < 128; w += 8) {
        int j = w * 32 + lane;
        float x = p[j * 3 + 0], y = p[j * 3 + 1], z = p[j * 3 + 2];
        float dax = __fsub_rn(cax, x), day = __fsub_rn(cay, y), daz = __fsub_rn(caz, z);
        float da = __fadd_rn(__fadd_rn(__fmul_rn(dax, dax), __fmul_rn(day, day)),
                             __fmul_rn(daz, daz));
        float dbx = __fsub_rn(cbx, x), dby = __fsub_rn(cby, y), dbz = __fsub_rn(cbz, z);
        float db = __fadd_rn(__fadd_rn(__fmul_rn(dbx, dbx), __fmul_rn(dby, dby)),
                             __fmul_rn(dbz, dbz));
        unsigned mA = __ballot_sync(0xffffffffu, !(da > R2A));
        unsigned mB = __ballot_sync(0xffffffffu, !(db > R2A));
        if (lane == 0) { smaskA[w] = mA; smaskB[w] = mB; }
    }
    __syncthreads();
    if (tid == 0) {
        int cnt = 0;
        for (int w = 0; w < 128 && cnt < 32; w++) {
            unsigned m = smaskA[w];
            while (m && cnt < 32) {
                int t = __ffs(m) - 1;
                m &= m - 1;
                sel[cnt++] = w * 32 + t;
            }
        }
        int c0 = sel[0];
        for (int j = cnt; j < 32; j++) sel[j] = c0;
    } else if (tid == 128) {
        int cnt = 0;
        for (int w = 0; w < 128 && cnt < 32; w++) {
            unsigned m = smaskB[w];
            while (m && cnt < 32) {
                int t = __ffs(m) - 1;
                m &= m - 1;
                sel[32 + cnt++] = w * 32 + t;
            }
        }
        int c0 = sel[32];
        for (int j = cnt; j < 32; j++) sel[32 + j] = c0;
    }
    __syncthreads();
    if (tid < 192) {
        int n = tid / 3, c = tid - n * 3;
        float cc = (n < 32) ? ctr[c] : ctr[3 + c];
        Ax[n * 3 + c] = p[sel[n] * 3 + c] - cc;
    }
    __syncthreads();

    // L1: 3 -> 64 for 64 rows
#pragma unroll
    for (int r = 0; r < 16; r++) {
        int lin = r * 256 + tid;
        int n = lin >> 6, o = lin & 63;
        float a = b10[o] + Ax[n * 3 + 0] * w10[o] + Ax[n * 3 + 1] * w10[64 + o] +
                  Ax[n * 3 + 2] * w10[128 + o];
        H1[n * P1 + o] = fmaxf(a, 0.f);
    }
    __syncthreads();

    const int g = lane >> 2, q = lane & 3;
    const int mi = warp >> 1, nh = warp & 1;
    const int m0 = mi * 16;

    // L2: 64x64x64 tf32 mma -> H2 (separate buffer; barrier before L3)
    {
        float d[4][4] = {};
        for (int k0 = 0; k0 < 64; k0 += 8) {
            uint32_t a0 = f2tf(H1[(m0 + g) * P1 + k0 + q]);
            uint32_t a1 = f2tf(H1[(m0 + g + 8) * P1 + k0 + q]);
            uint32_t a2 = f2tf(H1[(m0 + g) * P1 + k0 + q + 4]);
            uint32_t a3 = f2tf(H1[(m0 + g + 8) * P1 + k0 + q + 4]);
#pragma unroll
            for (int nt = 0; nt < 4; nt++) {
                int n0 = nh * 32 + nt * 8;
                uint32_t b0 = f2tf(w11[(k0 + q) * 64 + n0 + g]);
                uint32_t b1 = f2tf(w11[(k0 + q + 4) * 64 + n0 + g]);
                mma_tf32(d[nt], a0, a1, a2, a3, b0, b1);
            }
        }
#pragma unroll
        for (int nt = 0; nt < 4; nt++) {
            int c0 = nh * 32 + nt * 8 + q * 2;
            float bb0 = b11[c0], bb1 = b11[c0 + 1];
            H2[(m0 + g) * P1 + c0] = fmaxf(d[nt][0] + bb0, 0.f);
            H2[(m0 + g) * P1 + c0 + 1] = fmaxf(d[nt][1] + bb1, 0.f);
            H2[(m0 + g + 8) * P1 + c0] = fmaxf(d[nt][2] + bb0, 0.f);
            H2[(m0 + g + 8) * P1 + c0 + 1] = fmaxf(d[nt][3] + bb1, 0.f);
        }
    }
    __syncthreads();

    // L3: 64x128x64 tf32 mma with fused maxpool; Pm reuses H1
    float* Pm = H1;  // [4][128]
    {
        float d[8][4] = {};
        for (int k0 = 0; k0 < 64; k0 += 8) {
            uint32_t a0 = f2tf(H2[(m0 + g) * P1 + k0 + q]);
            uint32_t a1 = f2tf(H2[(m0 + g + 8) * P1 + k0 + q]);
            uint32_t a2 = f2tf(H2[(m0 + g) * P1 + k0 + q + 4]);
            uint32_t a3 = f2tf(H2[(m0 + g + 8) * P1 + k0 + q + 4]);
#pragma unroll
            for (int nt = 0; nt < 8; nt++) {
                int n0 = nh * 64 + nt * 8;
                uint32_t b0 = f2tf(w12[(k0 + q) * 128 + n0 + g]);
                uint32_t b1 = f2tf(w12[(k0 + q + 4) * 128 + n0 + g]);
                mma_tf32(d[nt], a0, a1, a2, a3, b0, b1);
            }
        }
        __syncthreads();  // H1 (=Pm) reads in L2 done; safe to overwrite
#pragma unroll
        for (int nt = 0; nt < 8; nt++) {
            float m0v = fmaxf(d[nt][0], d[nt][2]);
            float m1v = fmaxf(d[nt][1], d[nt][3]);
#pragma unroll
            for (int off = 4; off < 32; off <<= 1) {
                m0v = fmaxf(m0v, __shfl_xor_sync(0xffffffffu, m0v, off));
                m1v = fmaxf(m1v, __shfl_xor_sync(0xffffffffu, m1v, off));
            }
            if (g == 0) {
                int c0 = nh * 64 + nt * 8 + q * 2;
                Pm[mi * 128 + c0] = m0v;
                Pm[mi * 128 + c0 + 1] = m1v;
            }
        }
    }
    __syncthreads();
    {
        int h = tid >> 7, o = tid & 127;  // group half and channel
        float m = fmaxf(Pm[(h * 2) * 128 + o], Pm[(h * 2 + 1) * 128 + o]);
        g_l1f[((size_t)b * 512 + sp2 * 2 + h) * 128 + o] = fmaxf(m + b12[o], 0.f);
    }
}

// ---------------------------------------------------------------------------
// SA2: per (b,s): ball query (r=0.4, ns=64) over 512 pts.
// L1 via precomputed U2 gather; L2 (128->128) and L3 (128->256, fused maxpool)
// on tf32 mma. 64 rows = 4 m16 tiles; 8 warps = (4 m) x (2 n-halves).
// ---------------------------------------------------------------------------
#define P2 132  // padded pitch (mod 4 == 0) for 128-wide smem rows

__global__ __launch_bounds__(256) void sa2_kernel(
    const float* __restrict__ w20,
    const float* __restrict__ w21, const float* __restrict__ b21,
    const float* __restrict__ w22, const float* __restrict__ b22) {
    const int s = blockIdx.x, b = blockIdx.y;
    const int tid = threadIdx.x;
    const float* px = g_l1x + (size_t)b * 512 * 3;

    __shared__ __align__(16) float H[64 * P2];  // H1 -> H2 (in place)
    __shared__ float Pm[4 * 256];
    __shared__ unsigned smask[16];
    __shared__ int sel[64];
    __shared__ float ctr[3];
    __shared__ float dx3[64 * 3];

    if (tid < 3) ctr[tid] = g_l2x[((size_t)b * 128 + s) * 3 + tid];
    __syncthreads();
    const float cx = ctr[0], cy = ctr[1], cz = ctr[2];

    const int lane = tid & 31, warp = tid >> 5;
    for (int w = warp; w < 16; w += 8) {
        int j = w * 32 + lane;
        float dx = __fsub_rn(cx, px[j * 3 + 0]);
        float dy = __fsub_rn(cy, px[j * 3 + 1]);
        float dz = __fsub_rn(cz, px[j * 3 + 2]);
        float d = __fadd_rn(__fadd_rn(__fmul_rn(dx, dx), __fmul_rn(dy, dy)),
                            __fmul_rn(dz, dz));
        unsigned m = __ballot_sync(0xffffffffu, !(d > R2B));
        if (lane == 0) smask[w] = m;
    }
    __syncthreads();
    if (tid == 0) {
        int cnt = 0;
        for (int w = 0; w < 16 && cnt < 64; w++) {
            unsigned m = smask[w];
            while (m && cnt < 64) {
                int t = __ffs(m) - 1;
                m &= m - 1;
                sel[cnt++] = w * 32 + t;
            }
        }
        int c0 = sel[0];
        for (int j = cnt; j < 64; j++) sel[j] = c0;
    }
    __syncthreads();
    if (tid < 192) {
        int n = tid / 3, c = tid - n * 3;
        float cc = (c == 0) ? cx : ((c == 1) ? cy : cz);
        dx3[tid] = px[sel[n] * 3 + c] - cc;
    }
    __syncthreads();

    // L1: gather U2 + xyz contribution, relu. 8n x 4o per thread.
    {
        const int o0 = (tid & 31) * 4, n0 = (tid >> 5) * 8;
        float4 wxv = *(const float4*)(w20 + o0);
        float4 wyv = *(const float4*)(w20 + 128 + o0);
        float4 wzv = *(const float4*)(w20 + 256 + o0);
#pragma unroll
        for (int i = 0; i < 8; i++) {
            int n = n0 + i;
            float ddx = dx3[n * 3 + 0], ddy = dx3[n * 3 + 1], ddz = dx3[n * 3 + 2];
            float4 u = *(const float4*)(g_u2 + ((size_t)b * 512 + sel[n]) * 128 + o0);
            float4 r;
            r.x = fmaxf(u.x + ddx * wxv.x + ddy * wyv.x + ddz * wzv.x, 0.f);
            r.y = fmaxf(u.y + ddx * wxv.y + ddy * wyv.y + ddz * wzv.y, 0.f);
            r.z = fmaxf(u.z + ddx * wxv.z + ddy * wyv.z + ddz * wzv.z, 0.f);
            r.w = fmaxf(u.w + ddx * wxv.w + ddy * wyv.w + ddz * wzv.w, 0.f);
            *(float4*)(H + n * P2 + o0) = r;
        }
    }
    __syncthreads();

    const int g = lane >> 2, q = lane & 3;
    const int mi = warp >> 1, nh = warp & 1;
    const int m0 = mi * 16;

    // L2: 64x128x128 tf32 mma, in-place H update (barriers around writes)
    {
        float d[8][4] = {};
        for (int k0 = 0; k0 < 128; k0 += 8) {
            uint32_t a0 = f2tf(H[(m0 + g) * P2 + k0 + q]);
            uint32_t a1 = f2tf(H[(m0 + g + 8) * P2 + k0 + q]);
            uint32_t a2 = f2tf(H[(m0 + g) * P2 + k0 + q + 4]);
            uint32_t a3 = f2tf(H[(m0 + g + 8) * P2 + k0 + q + 4]);
#pragma unroll
            for (int nt = 0; nt < 8; nt++) {
                int n0 = nh * 64 + nt * 8;
                uint32_t b0 = f2tf(w21[(k0 + q) * 128 + n0 + g]);
                uint32_t b1 = f2tf(w21[(k0 + q + 4) * 128 + n0 + g]);
                mma_tf32(d[nt], a0, a1, a2, a3, b0, b1);
            }
        }
        __syncthreads();  // all H1 reads complete before overwrite
#pragma unroll
        for (int nt = 0; nt < 8; nt++) {
            int c0 = nh * 64 + nt * 8 + q * 2;
            float bb0 = b21[c0], bb1 = b21[c0 + 1];
            H[(m0 + g) * P2 + c0] = fmaxf(d[nt][0] + bb0, 0.f);
            H[(m0 + g) * P2 + c0 + 1] = fmaxf(d[nt][1] + bb1, 0.f);
            H[(m0 + g + 8) * P2 + c0] = fmaxf(d[nt][2] + bb0, 0.f);
            H[(m0 + g + 8) * P2 + c0 + 1] = fmaxf(d[nt][3] + bb1, 0.f);
        }
    }
    __syncthreads();

    // L3: 64x256x128 tf32 mma in two 128-col passes, fused maxpool -> Pm
    for (int pass = 0; pass < 2; pass++) {
        float d[8][4] = {};
        for (int k0 = 0; k0 < 128; k0 += 8) {
            uint32_t a0 = f2tf(H[(m0 + g) * P2 + k0 + q]);
            uint32_t a1 = f2tf(H[(m0 + g + 8) * P2 + k0 + q]);
            uint32_t a2 = f2tf(H[(m0 + g) * P2 + k0 + q + 4]);
            uint32_t a3 = f2tf(H[(m0 + g + 8) * P2 + k0 + q + 4]);
#pragma unroll
            for (int nt = 0; nt < 8; nt++) {
                int n0 = pass * 128 + nh * 64 + nt * 8;
                uint32_t b0 = f2tf(w22[(k0 + q) * 256 + n0 + g]);
                uint32_t b1 = f2tf(w22[(k0 + q + 4) * 256 + n0 + g]);
                mma_tf32(d[nt], a0, a1, a2, a3, b0, b1);
            }
        }
#pragma unroll
        for (int nt = 0; nt < 8; nt++) {
            float m0v = fmaxf(d[nt][0], d[nt][2]);
            float m1v = fmaxf(d[nt][1], d[nt][3]);
#pragma unroll
            for (int off = 4; off < 32; off <<= 1) {
                m0v = fmaxf(m0v, __shfl_xor_sync(0xffffffffu, m0v, off));
                m1v = fmaxf(m1v, __shfl_xor_sync(0xffffffffu, m1v, off));
            }
            if (g == 0) {
                int c0 = pass * 128 + nh * 64 + nt * 8 + q * 2;
                Pm[mi * 256 + c0] = m0v;
                Pm[mi * 256 + c0 + 1] = m1v;
            }
        }
    }
    __syncthreads();
    {
        int o = tid;
        float m = fmaxf(fmaxf(Pm[o], Pm[256 + o]), fmaxf(Pm[512 + o], Pm[768 + o]));
        g_l2f[((size_t)b * 128 + s) * 256 + o] = fmaxf(m + b22[o], 0.f);
    }
}

// ---------------------------------------------------------------------------
// SA3 input build: concat(l2x, l2f) -> [B,128,259]
// ---------------------------------------------------------------------------
__global__ __launch_bounds__(256) void sa3build_kernel() {
    const int b = blockIdx.x;
    for (int e = threadIdx.x; e < 128 * 259; e += blockDim.x) {
        int n = e / 259, c = e - n * 259;
        g_sa3in[(size_t)b * 128 * 259 + e] =
            (c < 3) ? g_l2x[((size_t)b * 128 + n) * 3 + c]
                    : g_l2f[((size_t)b * 128 + n) * 256 + (c - 3)];
    }
}

// ---------------------------------------------------------------------------
// Generic GEMM + bias (+optional relu), batch flattened into M.
// grid (M_total/64, O/64), block 256, tile 4n x 4o.
// ---------------------------------------------------------------------------
__global__ __launch_bounds__(256) void gemm_bias_kernel(const float* __restrict__ W,
                                                        const float* __restrict__ bias,
                                                        int K, int O, int which, int dorelu) {
    const int mblk = blockIdx.x, oblk = blockIdx.y;
    const float* A;
    float* C;
    if (which == 0) { A = g_sa3in; C = g_h3a; }
    else if (which == 1) { A = g_h3a; C = g_h3b; }
    else if (which == 2) { A = g_h3b; C = g_h3c; }
    else { A = g_l1f; C = g_u2; }

    const int tid = threadIdx.x;
    const int o0 = oblk * 64 + (tid & 15) * 4;
    const int nl0 = (tid >> 4) * 4;
    const int row0 = mblk * 64;

    __shared__ float As[64 * 33];
    float acc[4][4] = {};
    for (int kb = 0; kb < K; kb += 32) {
        const int w = min(32, K - kb);
        __syncthreads();
        for (int e = tid; e < 64 * 32; e += 256) {
            int r = e >> 5, cc = e & 31;
            As[r * 33 + cc] = (cc < w) ? A[(size_t)(row0 + r) * K + kb + cc] : 0.f;
        }
        __syncthreads();
        for (int c = 0; c < w; c++) {
            float4 bvv = *(const float4*)(W + (size_t)(kb + c) * O + o0);
#pragma unroll
            for (int i = 0; i < 4; i++) {
                float a = As[(nl0 + i) * 33 + c];
                acc[i][0] += a * bvv.x; acc[i][1] += a * bvv.y;
                acc[i][2] += a * bvv.z; acc[i][3] += a * bvv.w;
            }
        }
    }
#pragma unroll
    for (int i = 0; i < 4; i++)
#pragma unroll
        for (int j = 0; j < 4; j++) {
            float v = acc[i][j] + bias[o0 + j];
            if (dorelu) v = fmaxf(v, 0.f);
            C[(size_t)(row0 + nl0 + i) * O + o0 + j] = v;
        }
}

// ---------------------------------------------------------------------------
// Maxpool over the 128 rows of h3c -> g_g [B,1024]
// ---------------------------------------------------------------------------
__global__ __launch_bounds__(128) void maxpool_kernel() {
    const int b = blockIdx.x;
    const int o = blockIdx.y * 128 + threadIdx.x;
    float m = -1e30f;
    for (int n = 0; n < 128; n++)
        m = fmaxf(m, g_h3c[((size_t)b * 128 + n) * 1024 + o]);
    g_g[b * 1024 + o] = m;
}

// ---------------------------------------------------------------------------
// Heads
// ---------------------------------------------------------------------------
__global__ __launch_bounds__(256) void heads_kernel(
    const float* __restrict__ lw1, const float* __restrict__ lb1,
    const float* __restrict__ lw2, const float* __restrict__ lb2,
    const float* __restrict__ fw1, const float* __restrict__ fb1,
    const float* __restrict__ fw2, const float* __restrict__ fb2,
    const float* __restrict__ pos_mean, const float* __restrict__ pos_std,
    const float* __restrict__ rot_mean, const float* __restrict__ rot_std,
    float* __restrict__ out) {
    const int b = blockIdx.x;
    const int tid = threadIdx.x;
    __shared__ float gs[1024], h1s[256], f1s[512], res[18], lab[2];
    for (int e = tid; e < 1024; e += 256) gs[e] = g_g[b * 1024 + e];
    __syncthreads();
#pragma unroll
    for (int rep = 0; rep < 2; rep++) {
        int o = tid + rep * 256;
        float acc = fb1[o];
        for (int k = 0; k < 1024; k++) acc += gs[k] * fw1[k * 512 + o];
        f1s[o] = fmaxf(acc, 0.f);
    }
    {
        int o = tid;
        float acc = lb1[o];
        for (int k = 0; k < 1024; k++) acc += gs[k] * lw1[k * 256 + o];
        h1s[o] = fmaxf(acc, 0.f);
    }
    __syncthreads();
    if (tid < 18) {
        float acc = fb2[tid];
        for (int k = 0; k < 512; k++) acc += f1s[k] * fw2[k * 18 + tid];
        res[tid] = acc;
    } else if (tid < 20) {
        int j = tid - 18;
        float acc = lb2[j];
        for (int k = 0; k < 256; k++) acc += h1s[k] * lw2[k * 2 + j];
        lab[j] = 1.f / (1.f + expf(-acc));
    }
    __syncthreads();
    if (tid < 20) {
        float v;
        if (tid < 2) v = lab[tid];
        else if (tid < 5) { int i = tid - 2; v = res[i] * pos_std[i] + pos_mean[i]; }
        else if (tid < 11) { int i = tid - 5; v = res[3 + i] * rot_std[i] + rot_mean[i]; }
        else if (tid < 14) { int i = tid - 11; v = res[9 + i] * pos_std[i] + pos_mean[i]; }
        else { int i = tid - 14; v = res[12 + i] * rot_std[i] + rot_mean[i]; }
        out[b * 20 + tid] = v;
    }
}

// ---------------------------------------------------------------------------
extern "C" void kernel_launch(void* const* d_in, const int* in_sizes, int n_in,
                              void* d_out, int out_size) {
    (void)in_sizes; (void)n_in; (void)out_size;
    const float* pts = (const float*)d_in[0];
    const float* w10 = (const float*)d_in[1];  const float* b10 = (const float*)d_in[2];
    const float* w11 = (const float*)d_in[3];  const float* b11 = (const float*)d_in[4];
    const float* w12 = (const float*)d_in[5];  const float* b12 = (const float*)d_in[6];
    const float* w20 = (const float*)d_in[7];  const float* b20 = (const float*)d_in[8];
    const float* w21 = (const float*)d_in[9];  const float* b21 = (const float*)d_in[10];
    const float* w22 = (const float*)d_in[11]; const float* b22 = (const float*)d_in[12];
    const float* w30 = (const float*)d_in[13]; const float* b30 = (const float*)d_in[14];
    const float* w31 = (const float*)d_in[15]; const float* b31 = (const float*)d_in[16];
    const float* w32 = (const float*)d_in[17]; const float* b32 = (const float*)d_in[18];
    const float* lw1 = (const float*)d_in[19]; const float* lb1 = (const float*)d_in[20];
    const float* lw2 = (const float*)d_in[21]; const float* lb2 = (const float*)d_in[22];
    const float* fw1 = (const float*)d_in[23]; const float* fb1 = (const float*)d_in[24];
    const float* fw2 = (const float*)d_in[25]; const float* fb2 = (const float*)d_in[26];
    const float* pos_mean = (const float*)d_in[27];
    const float* pos_std  = (const float*)d_in[28];
    const float* rot_mean = (const float*)d_in[29];
    const float* rot_std  = (const float*)d_in[30];
    float* out = (float*)d_out;

    cudaFuncSetAttribute(fps_kernel, cudaFuncAttributeMaxDynamicSharedMemorySize,
                         NPTS * 3 * 4 + 1024);

    fps_kernel<<<BATCH, 1024, NPTS * 3 * 4 + 768>>>(pts, NPTS, 512, 0);
    sa1_kernel<<<dim3(256, BATCH), 256>>>(pts, w10, b10, w11, b11, w12, b12);
    fps_kernel<<<BATCH, 512, 512 * 3 * 4 + 768>>>(pts, 512, 128, 1);
    gemm_bias_kernel<<<dim3(BATCH * 512 / 64, 2), 256>>>(w20 + 3 * 128, b20, 128, 128, 3, 0);
    sa2_kernel<<<dim3(128, BATCH), 256>>>(w20, w21, b21, w22, b22);
    sa3build_kernel<<<BATCH, 256>>>();
    gemm_bias_kernel<<<dim3(BATCH * 128 / 64, 4), 256>>>(w30, b30, 259, 256, 0, 1);
    gemm_bias_kernel<<<dim3(BATCH * 128 / 64, 8), 256>>>(w31, b31, 256, 512, 1, 1);
    gemm_bias_kernel<<<dim3(BATCH * 128 / 64, 16), 256>>>(w32, b32, 512, 1024, 2, 1);
    maxpool_kernel<<<dim3(BATCH, 8), 128>>>();
    heads_kernel<<<BATCH, 256>>>(lw1, lb1, lw2, lb2, fw1, fb1, fw2, fb2,
                                 pos_mean, pos_std, rot_mean, rot_std, out);
}

// round 8
// speedup vs baseline: 2.3305x; 1.1408x over previous
#include <cuda_runtime.h>
#include <cuda_bf16.h>
#include <stdint.h>
#include <math.h>

// ---------------------------------------------------------------------------
// PointNet++ grasp net forward. B=16, N=4096.
// FPS1 -> SA1 -> FPS2 -> U2(mma) -> SA2 -> SA3(mma GEMMs, fused maxpool) -> heads
// All large GEMMs on tensor cores (tf32 mma.sync, fp32 accumulate).
// ---------------------------------------------------------------------------

#define BATCH 16
#define NPTS 4096

// exact f32 thresholds as JAX sees them (python double radius*radius -> f32)
#define R2A ((float)(0.2 * 0.2))
#define R2B ((float)(0.4 * 0.4))

// ------------------------- device scratch (static) -------------------------
__device__ __align__(16) float g_l1x[BATCH * 512 * 3];
__device__ __align__(16) float g_l1f[BATCH * 512 * 128];
__device__ __align__(16) float g_u2[BATCH * 512 * 128];   // l1f @ w20[3:] + b20
__device__ __align__(16) float g_l2x[BATCH * 128 * 3];
__device__ __align__(16) float g_l2f[BATCH * 128 * 256];
__device__ __align__(16) float g_sa3in[BATCH * 128 * 259];
__device__ __align__(16) float g_h3a[BATCH * 128 * 256];
__device__ __align__(16) float g_h3b[BATCH * 128 * 512];
__device__ __align__(16) float g_pm[BATCH * 2 * 1024];    // 64-row maxpool partials

// ------------------------- tf32 mma helpers --------------------------------
__device__ __forceinline__ uint32_t f2tf(float v) {
    uint32_t r;
    asm("cvt.rna.tf32.f32 %0, %1;" : "=r"(r) : "f"(v));
    return r;
}
__device__ __forceinline__ void mma_tf32(float* d, uint32_t a0, uint32_t a1,
                                         uint32_t a2, uint32_t a3,
                                         uint32_t b0, uint32_t b1) {
    asm volatile(
        "mma.sync.aligned.m16n8k8.row.col.f32.tf32.tf32.f32 "
        "{%0,%1,%2,%3}, {%4,%5,%6,%7}, {%8,%9}, {%0,%1,%2,%3};"
        : "+f"(d[0]), "+f"(d[1]), "+f"(d[2]), "+f"(d[3])
        : "r"(a0), "r"(a1), "r"(a2), "r"(a3), "r"(b0), "r"(b1));
}

// ---------------------------------------------------------------------------
// FPS: one block per batch. ONE barrier per iteration (parity-double-buffered
// candidates; every warp reduces them so all threads compute `far` locally).
// Exact jnp semantics: dist init 1e10, first-index tie-break, no FMA fusion.
// ---------------------------------------------------------------------------
extern __shared__ float fps_sm[];

__global__ __launch_bounds__(1024) void fps_kernel(const float* __restrict__ pts_in,
                                                   int n, int S, int phase) {
    const int b = blockIdx.x;
    const float* p = (phase == 0 ? pts_in : g_l1x) + (size_t)b * n * 3;
    float* outxyz = (phase == 0 ? g_l1x : g_l2x);

    const int tid = threadIdx.x, BT = blockDim.x;
    float* sp = fps_sm;
    float* rv = fps_sm + n * 3;
    int* ri = (int*)(rv + 64);

    for (int e = tid; e < n * 3; e += BT) sp[e] = p[e];

    const int PT = n / BT;
    float px[4], py[4], pz[4], dd[4];
#pragma unroll
    for (int k = 0; k < 4; k++) {
        if (k < PT) {
            int i = tid + k * BT;
            px[k] = p[i * 3 + 0];
            py[k] = p[i * 3 + 1];
            pz[k] = p[i * 3 + 2];
            dd[k] = 1e10f;
        }
    }
    __syncthreads();

    const int lane = tid & 31, wid = tid >> 5, nw = BT >> 5;
    const int lsel = lane & (nw - 1);
    int far = 0;

    for (int s = 0; s < S; s++) {
        const float fx = sp[far * 3 + 0], fy = sp[far * 3 + 1], fz = sp[far * 3 + 2];
        if (tid == 0) {
            float* o = outxyz + ((size_t)b * S + s) * 3;
            o[0] = fx; o[1] = fy; o[2] = fz;
        }
        float bv = -1.0f;
        int bi = 0x7fffffff;
#pragma unroll
        for (int k = 0; k < 4; k++) {
            if (k < PT) {
                float dx = __fsub_rn(px[k], fx);
                float dy = __fsub_rn(py[k], fy);
                float dz = __fsub_rn(pz[k], fz);
                float d = __fadd_rn(__fadd_rn(__fmul_rn(dx, dx), __fmul_rn(dy, dy)),
                                    __fmul_rn(dz, dz));
                float ndv = fminf(dd[k], d);
                dd[k] = ndv;
                if (ndv > bv) { bv = ndv; bi = tid + k * BT; }
            }
        }
#pragma unroll
        for (int off = 16; off > 0; off >>= 1) {
            float ov = __shfl_down_sync(0xffffffffu, bv, off);
            int oi = __shfl_down_sync(0xffffffffu, bi, off);
            if (ov > bv || (ov == bv && oi < bi)) { bv = ov; bi = oi; }
        }
        const int po = (s & 1) * 32;
        if (lane == 0) { rv[po + wid] = bv; ri[po + wid] = bi; }
        __syncthreads();
        float v = rv[po + lsel];
        int i2 = ri[po + lsel];
#pragma unroll
        for (int off = 16; off > 0; off >>= 1) {
            float ov = __shfl_xor_sync(0xffffffffu, v, off);
            int oi = __shfl_xor_sync(0xffffffffu, i2, off);
            if (ov > v || (ov == v && oi < i2)) { v = ov; i2 = oi; }
        }
        far = i2;
    }
}

// ---------------------------------------------------------------------------
// SA1: TWO groups per block (256 thr). Ball query r=0.2 ns=32 over 4096 pts;
// L1 (3->64) scalar; L2 (64->64) and L3 (64->128, fused maxpool) on tf32 mma.
// ---------------------------------------------------------------------------
#define P1 68  // padded pitch for 64-wide smem rows

__global__ __launch_bounds__(256) void sa1_kernel(
    const float* __restrict__ pts,
    const float* __restrict__ w10, const float* __restrict__ b10,
    const float* __restrict__ w11, const float* __restrict__ b11,
    const float* __restrict__ w12, const float* __restrict__ b12) {
    const int sp2 = blockIdx.x;
    const int b = blockIdx.y;
    const int tid = threadIdx.x;
    const float* p = pts + (size_t)b * NPTS * 3;

    __shared__ unsigned smaskA[128], smaskB[128];
    __shared__ int sel[64];
    __shared__ float ctr[6];
    __shared__ float Ax[64 * 3];
    __shared__ float H1[64 * P1];  // reused as Pm[4][128] after L2 reads
    __shared__ float H2[64 * P1];

    if (tid < 6) ctr[tid] = g_l1x[((size_t)b * 512 + sp2 * 2) * 3 + tid];
    __syncthreads();
    const float cax = ctr[0], cay = ctr[1], caz = ctr[2];
    const float cbx = ctr[3], cby = ctr[4], cbz = ctr[5];

    const int lane = tid & 31, warp = tid >> 5;
    for (int w = warp; w < 128; w += 8) {
        int j = w * 32 + lane;
        float x = p[j * 3 + 0], y = p[j * 3 + 1], z = p[j * 3 + 2];
        float dax = __fsub_rn(cax, x), day = __fsub_rn(cay, y), daz = __fsub_rn(caz, z);
        float da = __fadd_rn(__fadd_rn(__fmul_rn(dax, dax), __fmul_rn(day, day)),
                             __fmul_rn(daz, daz));
        float dbx = __fsub_rn(cbx, x), dby = __fsub_rn(cby, y), dbz = __fsub_rn(cbz, z);
        float db = __fadd_rn(__fadd_rn(__fmul_rn(dbx, dbx), __fmul_rn(dby, dby)),
                             __fmul_rn(dbz, dbz));
        unsigned mA = __ballot_sync(0xffffffffu, !(da > R2A));
        unsigned mB = __ballot_sync(0xffffffffu, !(db > R2A));
        if (lane == 0) { smaskA[w] = mA; smaskB[w] = mB; }
    }
    __syncthreads();
    if (tid == 0) {
        int cnt = 0;
        for (int w = 0; w < 128 && cnt < 32; w++) {
            unsigned m = smaskA[w];
            while (m && cnt < 32) {
                int t = __ffs(m) - 1;
                m &= m - 1;
                sel[cnt++] = w * 32 + t;
            }
        }
        int c0 = sel[0];
        for (int j = cnt; j < 32; j++) sel[j] = c0;
    } else if (tid == 128) {
        int cnt = 0;
        for (int w = 0; w < 128 && cnt < 32; w++) {
            unsigned m = smaskB[w];
            while (m && cnt < 32) {
                int t = __ffs(m) - 1;
                m &= m - 1;
                sel[32 + cnt++] = w * 32 + t;
            }
        }
        int c0 = sel[32];
        for (int j = cnt; j < 32; j++) sel[32 + j] = c0;
    }
    __syncthreads();
    if (tid < 192) {
        int n = tid / 3, c = tid - n * 3;
        float cc = (n < 32) ? ctr[c] : ctr[3 + c];
        Ax[n * 3 + c] = p[sel[n] * 3 + c] - cc;
    }
    __syncthreads();

    // L1: 3 -> 64 for 64 rows
#pragma unroll
    for (int r = 0; r < 16; r++) {
        int lin = r * 256 + tid;
        int n = lin >> 6, o = lin & 63;
        float a = b10[o] + Ax[n * 3 + 0] * w10[o] + Ax[n * 3 + 1] * w10[64 + o] +
                  Ax[n * 3 + 2] * w10[128 + o];
        H1[n * P1 + o] = fmaxf(a, 0.f);
    }
    __syncthreads();

    const int g = lane >> 2, q = lane & 3;
    const int mi = warp >> 1, nh = warp & 1;
    const int m0 = mi * 16;

    // L2: 64x64x64 tf32 mma -> H2
    {
        float d[4][4] = {};
        for (int k0 = 0; k0 < 64; k0 += 8) {
            uint32_t a0 = f2tf(H1[(m0 + g) * P1 + k0 + q]);
            uint32_t a1 = f2tf(H1[(m0 + g + 8) * P1 + k0 + q]);
            uint32_t a2 = f2tf(H1[(m0 + g) * P1 + k0 + q + 4]);
            uint32_t a3 = f2tf(H1[(m0 + g + 8) * P1 + k0 + q + 4]);
#pragma unroll
            for (int nt = 0; nt < 4; nt++) {
                int n0 = nh * 32 + nt * 8;
                uint32_t b0 = f2tf(w11[(k0 + q) * 64 + n0 + g]);
                uint32_t b1 = f2tf(w11[(k0 + q + 4) * 64 + n0 + g]);
                mma_tf32(d[nt], a0, a1, a2, a3, b0, b1);
            }
        }
#pragma unroll
        for (int nt = 0; nt < 4; nt++) {
            int c0 = nh * 32 + nt * 8 + q * 2;
            float bb0 = b11[c0], bb1 = b11[c0 + 1];
            H2[(m0 + g) * P1 + c0] = fmaxf(d[nt][0] + bb0, 0.f);
            H2[(m0 + g) * P1 + c0 + 1] = fmaxf(d[nt][1] + bb1, 0.f);
            H2[(m0 + g + 8) * P1 + c0] = fmaxf(d[nt][2] + bb0, 0.f);
            H2[(m0 + g + 8) * P1 + c0 + 1] = fmaxf(d[nt][3] + bb1, 0.f);
        }
    }
    __syncthreads();

    // L3: 64x128x64 tf32 mma with fused maxpool; Pm reuses H1
    float* Pm = H1;  // [4][128]
    {
        float d[8][4] = {};
        for (int k0 = 0; k0 < 64; k0 += 8) {
            uint32_t a0 = f2tf(H2[(m0 + g) * P1 + k0 + q]);
            uint32_t a1 = f2tf(H2[(m0 + g + 8) * P1 + k0 + q]);
            uint32_t a2 = f2tf(H2[(m0 + g) * P1 + k0 + q + 4]);
            uint32_t a3 = f2tf(H2[(m0 + g + 8) * P1 + k0 + q + 4]);
#pragma unroll
            for (int nt = 0; nt < 8; nt++) {
                int n0 = nh * 64 + nt * 8;
                uint32_t b0 = f2tf(w12[(k0 + q) * 128 + n0 + g]);
                uint32_t b1 = f2tf(w12[(k0 + q + 4) * 128 + n0 + g]);
                mma_tf32(d[nt], a0, a1, a2, a3, b0, b1);
            }
        }
        __syncthreads();  // H1 (=Pm) reads in L2 done; safe to overwrite
#pragma unroll
        for (int nt = 0; nt < 8; nt++) {
            float m0v = fmaxf(d[nt][0], d[nt][2]);
            float m1v = fmaxf(d[nt][1], d[nt][3]);
#pragma unroll
            for (int off = 4; off < 32; off <<= 1) {
                m0v = fmaxf(m0v, __shfl_xor_sync(0xffffffffu, m0v, off));
                m1v = fmaxf(m1v, __shfl_xor_sync(0xffffffffu, m1v, off));
            }
            if (g == 0) {
                int c0 = nh * 64 + nt * 8 + q * 2;
                Pm[mi * 128 + c0] = m0v;
                Pm[mi * 128 + c0 + 1] = m1v;
            }
        }
    }
    __syncthreads();
    {
        int h = tid >> 7, o = tid & 127;  // group half and channel
        float m = fmaxf(Pm[(h * 2) * 128 + o], Pm[(h * 2 + 1) * 128 + o]);
        g_l1f[((size_t)b * 512 + sp2 * 2 + h) * 128 + o] = fmaxf(m + b12[o], 0.f);
    }
}

// ---------------------------------------------------------------------------
// SA2: per (b,s): ball query (r=0.4, ns=64) over 512 pts.
// L1 via precomputed U2 gather; L2 (128->128) and L3 (128->256, fused maxpool)
// on tf32 mma.
// ---------------------------------------------------------------------------
#define P2 132  // padded pitch (mod 4 == 0) for 128-wide smem rows

__global__ __launch_bounds__(256) void sa2_kernel(
    const float* __restrict__ w20,
    const float* __restrict__ w21, const float* __restrict__ b21,
    const float* __restrict__ w22, const float* __restrict__ b22) {
    const int s = blockIdx.x, b = blockIdx.y;
    const int tid = threadIdx.x;
    const float* px = g_l1x + (size_t)b * 512 * 3;

    __shared__ __align__(16) float H[64 * P2];  // H1 -> H2 (in place)
    __shared__ float Pm[4 * 256];
    __shared__ unsigned smask[16];
    __shared__ int sel[64];
    __shared__ float ctr[3];
    __shared__ float dx3[64 * 3];

    if (tid < 3) ctr[tid] = g_l2x[((size_t)b * 128 + s) * 3 + tid];
    __syncthreads();
    const float cx = ctr[0], cy = ctr[1], cz = ctr[2];

    const int lane = tid & 31, warp = tid >> 5;
    for (int w = warp; w < 16; w += 8) {
        int j = w * 32 + lane;
        float dx = __fsub_rn(cx, px[j * 3 + 0]);
        float dy = __fsub_rn(cy, px[j * 3 + 1]);
        float dz = __fsub_rn(cz, px[j * 3 + 2]);
        float d = __fadd_rn(__fadd_rn(__fmul_rn(dx, dx), __fmul_rn(dy, dy)),
                            __fmul_rn(dz, dz));
        unsigned m = __ballot_sync(0xffffffffu, !(d > R2B));
        if (lane == 0) smask[w] = m;
    }
    __syncthreads();
    if (tid == 0) {
        int cnt = 0;
        for (int w = 0; w < 16 && cnt < 64; w++) {
            unsigned m = smask[w];
            while (m && cnt < 64) {
                int t = __ffs(m) - 1;
                m &= m - 1;
                sel[cnt++] = w * 32 + t;
            }
        }
        int c0 = sel[0];
        for (int j = cnt; j < 64; j++) sel[j] = c0;
    }
    __syncthreads();
    if (tid < 192) {
        int n = tid / 3, c = tid - n * 3;
        float cc = (c == 0) ? cx : ((c == 1) ? cy : cz);
        dx3[tid] = px[sel[n] * 3 + c] - cc;
    }
    __syncthreads();

    // L1: gather U2 + xyz contribution, relu. 8n x 4o per thread.
    {
        const int o0 = (tid & 31) * 4, n0 = (tid >> 5) * 8;
        float4 wxv = *(const float4*)(w20 + o0);
        float4 wyv = *(const float4*)(w20 + 128 + o0);
        float4 wzv = *(const float4*)(w20 + 256 + o0);
#pragma unroll
        for (int i = 0; i < 8; i++) {
            int n = n0 + i;
            float ddx = dx3[n * 3 + 0], ddy = dx3[n * 3 + 1], ddz = dx3[n * 3 + 2];
            float4 u = *(const float4*)(g_u2 + ((size_t)b * 512 + sel[n]) * 128 + o0);
            float4 r;
            r.x = fmaxf(u.x + ddx * wxv.x + ddy * wyv.x + ddz * wzv.x, 0.f);
            r.y = fmaxf(u.y + ddx * wxv.y + ddy * wyv.y + ddz * wzv.y, 0.f);
            r.z = fmaxf(u.z + ddx * wxv.z + ddy * wyv.z + ddz * wzv.z, 0.f);
            r.w = fmaxf(u.w + ddx * wxv.w + ddy * wyv.w + ddz * wzv.w, 0.f);
            *(float4*)(H + n * P2 + o0) = r;
        }
    }
    __syncthreads();

    const int g = lane >> 2, q = lane & 3;
    const int mi = warp >> 1, nh = warp & 1;
    const int m0 = mi * 16;

    // L2: 64x128x128 tf32 mma, in-place H update (barriers around writes)
    {
        float d[8][4] = {};
        for (int k0 = 0; k0 < 128; k0 += 8) {
            uint32_t a0 = f2tf(H[(m0 + g) * P2 + k0 + q]);
            uint32_t a1 = f2tf(H[(m0 + g + 8) * P2 + k0 + q]);
            uint32_t a2 = f2tf(H[(m0 + g) * P2 + k0 + q + 4]);
            uint32_t a3 = f2tf(H[(m0 + g + 8) * P2 + k0 + q + 4]);
#pragma unroll
            for (int nt = 0; nt < 8; nt++) {
                int n0 = nh * 64 + nt * 8;
                uint32_t b0 = f2tf(w21[(k0 + q) * 128 + n0 + g]);
                uint32_t b1 = f2tf(w21[(k0 + q + 4) * 128 + n0 + g]);
                mma_tf32(d[nt], a0, a1, a2, a3, b0, b1);
            }
        }
        __syncthreads();
#pragma unroll
        for (int nt = 0; nt < 8; nt++) {
            int c0 = nh * 64 + nt * 8 + q * 2;
            float bb0 = b21[c0], bb1 = b21[c0 + 1];
            H[(m0 + g) * P2 + c0] = fmaxf(d[nt][0] + bb0, 0.f);
            H[(m0 + g) * P2 + c0 + 1] = fmaxf(d[nt][1] + bb1, 0.f);
            H[(m0 + g + 8) * P2 + c0] = fmaxf(d[nt][2] + bb0, 0.f);
            H[(m0 + g + 8) * P2 + c0 + 1] = fmaxf(d[nt][3] + bb1, 0.f);
        }
    }
    __syncthreads();

    // L3: 64x256x128 tf32 mma in two 128-col passes, fused maxpool -> Pm
    for (int pass = 0; pass < 2; pass++) {
        float d[8][4] = {};
        for (int k0 = 0; k0 < 128; k0 += 8) {
            uint32_t a0 = f2tf(H[(m0 + g) * P2 + k0 + q]);
            uint32_t a1 = f2tf(H[(m0 + g + 8) * P2 + k0 + q]);
            uint32_t a2 = f2tf(H[(m0 + g) * P2 + k0 + q + 4]);
            uint32_t a3 = f2tf(H[(m0 + g + 8) * P2 + k0 + q + 4]);
#pragma unroll
            for (int nt = 0; nt < 8; nt++) {
                int n0 = pass * 128 + nh * 64 + nt * 8;
                uint32_t b0 = f2tf(w22[(k0 + q) * 256 + n0 + g]);
                uint32_t b1 = f2tf(w22[(k0 + q + 4) * 256 + n0 + g]);
                mma_tf32(d[nt], a0, a1, a2, a3, b0, b1);
            }
        }
#pragma unroll
        for (int nt = 0; nt < 8; nt++) {
            float m0v = fmaxf(d[nt][0], d[nt][2]);
            float m1v = fmaxf(d[nt][1], d[nt][3]);
#pragma unroll
            for (int off = 4; off < 32; off <<= 1) {
                m0v = fmaxf(m0v, __shfl_xor_sync(0xffffffffu, m0v, off));
                m1v = fmaxf(m1v, __shfl_xor_sync(0xffffffffu, m1v, off));
            }
            if (g == 0) {
                int c0 = pass * 128 + nh * 64 + nt * 8 + q * 2;
                Pm[mi * 256 + c0] = m0v;
                Pm[mi * 256 + c0 + 1] = m1v;
            }
        }
    }
    __syncthreads();
    {
        int o = tid;
        float m = fmaxf(fmaxf(Pm[o], Pm[256 + o]), fmaxf(Pm[512 + o], Pm[768 + o]));
        g_l2f[((size_t)b * 128 + s) * 256 + o] = fmaxf(m + b22[o], 0.f);
    }
}

// ---------------------------------------------------------------------------
// SA3 input build: concat(l2x, l2f) -> [B,128,259]
// ---------------------------------------------------------------------------
__global__ __launch_bounds__(256) void sa3build_kernel() {
    const int b = blockIdx.x;
    for (int e = threadIdx.x; e < 128 * 259; e += blockDim.x) {
        int n = e / 259, c = e - n * 259;
        g_sa3in[(size_t)b * 128 * 259 + e] =
            (c < 3) ? g_l2x[((size_t)b * 128 + n) * 3 + c]
                    : g_l2f[((size_t)b * 128 + n) * 256 + (c - 3)];
    }
}

// ---------------------------------------------------------------------------
// tf32 mma GEMM + bias (+relu), batch flattened into M.
// grid (M_total/64, O/64), block 256 (8 warps = 4 m-tiles x 2 n-halves).
// which: 0 sa3in->h3a (K=259,O=256), 1 h3a->h3b (256,512),
//        2 h3b->maxpool partials g_pm (512,1024), 3 l1f->u2 (128,128)
// For K not a multiple of 32 the A stage is zero-padded and the B row index
// is clamped (product is 0 there, so any in-bounds B value is fine).
// ---------------------------------------------------------------------------
__global__ __launch_bounds__(256) void gemm_mma_kernel(const float* __restrict__ W,
                                                       const float* __restrict__ bias,
                                                       int K, int O, int which, int dorelu) {
    const int mblk = blockIdx.x, oblk = blockIdx.y;
    const float* A;
    float* C;
    if (which == 0) { A = g_sa3in; C = g_h3a; }
    else if (which == 1) { A = g_h3a; C = g_h3b; }
    else if (which == 2) { A = g_h3b; C = nullptr; }
    else { A = g_l1f; C = g_u2; }

    const int row0 = mblk * 64;
    const int tid = threadIdx.x, lane = tid & 31, warp = tid >> 5;
    const int g = lane >> 2, q = lane & 3;
    const int mi = warp >> 1, nh = warp & 1, m0 = mi * 16;
    const int ob = oblk * 64;

    __shared__ __align__(16) float As[64 * 36];  // pitch 36 -> conflict-free
    __shared__ float Pms[4 * 64];
    float d[4][4] = {};
    for (int kb = 0; kb < K; kb += 32) {
        const int w = min(32, K - kb);
        __syncthreads();
        for (int e = tid; e < 64 * 32; e += 256) {
            int r = e >> 5, cc = e & 31;
            As[r * 36 + cc] = (cc < w) ? A[(size_t)(row0 + r) * K + kb + cc] : 0.f;
        }
        __syncthreads();
#pragma unroll
        for (int k0 = 0; k0 < 32; k0 += 8) {
            uint32_t a0 = f2tf(As[(m0 + g) * 36 + k0 + q]);
            uint32_t a1 = f2tf(As[(m0 + g + 8) * 36 + k0 + q]);
            uint32_t a2 = f2tf(As[(m0 + g) * 36 + k0 + q + 4]);
            uint32_t a3 = f2tf(As[(m0 + g + 8) * 36 + k0 + q + 4]);
            int kr0 = kb + k0 + q, kr1 = kb + k0 + q + 4;
            int kc0 = kr0 < K ? kr0 : K - 1;
            int kc1 = kr1 < K ? kr1 : K - 1;
#pragma unroll
            for (int nt = 0; nt < 4; nt++) {
                int n0 = ob + nh * 32 + nt * 8;
                uint32_t b0 = f2tf(W[(size_t)kc0 * O + n0 + g]);
                uint32_t b1 = f2tf(W[(size_t)kc1 * O + n0 + g]);
                mma_tf32(d[nt], a0, a1, a2, a3, b0, b1);
            }
        }
    }
    if (which != 2) {
#pragma unroll
        for (int nt = 0; nt < 4; nt++) {
            int c0 = ob + nh * 32 + nt * 8 + q * 2;
            float bb0 = bias[c0], bb1 = bias[c0 + 1];
            float v00 = d[nt][0] + bb0, v01 = d[nt][1] + bb1;
            float v10 = d[nt][2] + bb0, v11 = d[nt][3] + bb1;
            if (dorelu) {
                v00 = fmaxf(v00, 0.f); v01 = fmaxf(v01, 0.f);
                v10 = fmaxf(v10, 0.f); v11 = fmaxf(v11, 0.f);
            }
            C[(size_t)(row0 + m0 + g) * O + c0] = v00;
            C[(size_t)(row0 + m0 + g) * O + c0 + 1] = v01;
            C[(size_t)(row0 + m0 + g + 8) * O + c0] = v10;
            C[(size_t)(row0 + m0 + g + 8) * O + c0 + 1] = v11;
        }
    } else {
        // fused bias+relu then max over this block's 64 rows -> g_pm
#pragma unroll
        for (int nt = 0; nt < 4; nt++) {
            int c0l = nh * 32 + nt * 8 + q * 2;
            int c0 = ob + c0l;
            float bb0 = bias[c0], bb1 = bias[c0 + 1];
            float m0v = fmaxf(fmaxf(d[nt][0] + bb0, 0.f), fmaxf(d[nt][2] + bb0, 0.f));
            float m1v = fmaxf(fmaxf(d[nt][1] + bb1, 0.f), fmaxf(d[nt][3] + bb1, 0.f));
#pragma unroll
            for (int off = 4; off < 32; off <<= 1) {
                m0v = fmaxf(m0v, __shfl_xor_sync(0xffffffffu, m0v, off));
                m1v = fmaxf(m1v, __shfl_xor_sync(0xffffffffu, m1v, off));
            }
            if (g == 0) {
                Pms[mi * 64 + c0l] = m0v;
                Pms[mi * 64 + c0l + 1] = m1v;
            }
        }
        __syncthreads();
        if (tid < 64) {
            float m = fmaxf(fmaxf(Pms[tid], Pms[64 + tid]),
                            fmaxf(Pms[128 + tid], Pms[192 + tid]));
            g_pm[(size_t)mblk * 1024 + ob + tid] = m;  // mblk = batch*2 + half
        }
    }
}

// ---------------------------------------------------------------------------
// Heads: combine 2 maxpool partials -> g; then FC heads.
// ---------------------------------------------------------------------------
__global__ __launch_bounds__(256) void heads_kernel(
    const float* __restrict__ lw1, const float* __restrict__ lb1,
    const float* __restrict__ lw2, const float* __restrict__ lb2,
    const float* __restrict__ fw1, const float* __restrict__ fb1,
    const float* __restrict__ fw2, const float* __restrict__ fb2,
    const float* __restrict__ pos_mean, const float* __restrict__ pos_std,
    const float* __restrict__ rot_mean, const float* __restrict__ rot_std,
    float* __restrict__ out) {
    const int b = blockIdx.x;
    const int tid = threadIdx.x;
    __shared__ float gs[1024], h1s[256], f1s[512], res[18], lab[2];
    for (int e = tid; e < 1024; e += 256)
        gs[e] = fmaxf(g_pm[(size_t)(b * 2) * 1024 + e],
                      g_pm[(size_t)(b * 2 + 1) * 1024 + e]);
    __syncthreads();
#pragma unroll
    for (int rep = 0; rep < 2; rep++) {
        int o = tid + rep * 256;
        float acc = fb1[o];
        for (int k = 0; k < 1024; k++) acc += gs[k] * fw1[k * 512 + o];
        f1s[o] = fmaxf(acc, 0.f);
    }
    {
        int o = tid;
        float acc = lb1[o];
        for (int k = 0; k < 1024; k++) acc += gs[k] * lw1[k * 256 + o];
        h1s[o] = fmaxf(acc, 0.f);
    }
    __syncthreads();
    if (tid < 18) {
        float acc = fb2[tid];
        for (int k = 0; k < 512; k++) acc += f1s[k] * fw2[k * 18 + tid];
        res[tid] = acc;
    } else if (tid < 20) {
        int j = tid - 18;
        float acc = lb2[j];
        for (int k = 0; k < 256; k++) acc += h1s[k] * lw2[k * 2 + j];
        lab[j] = 1.f / (1.f + expf(-acc));
    }
    __syncthreads();
    if (tid < 20) {
        float v;
        if (tid < 2) v = lab[tid];
        else if (tid < 5) { int i = tid - 2; v = res[i] * pos_std[i] + pos_mean[i]; }
        else if (tid < 11) { int i = tid - 5; v = res[3 + i] * rot_std[i] + rot_mean[i]; }
        else if (tid < 14) { int i = tid - 11; v = res[9 + i] * pos_std[i] + pos_mean[i]; }
        else { int i = tid - 14; v = res[12 + i] * rot_std[i] + rot_mean[i]; }
        out[b * 20 + tid] = v;
    }
}

// ---------------------------------------------------------------------------
extern "C" void kernel_launch(void* const* d_in, const int* in_sizes, int n_in,
                              void* d_out, int out_size) {
    (void)in_sizes; (void)n_in; (void)out_size;
    const float* pts = (const float*)d_in[0];
    const float* w10 = (const float*)d_in[1];  const float* b10 = (const float*)d_in[2];
    const float* w11 = (const float*)d_in[3];  const float* b11 = (const float*)d_in[4];
    const float* w12 = (const float*)d_in[5];  const float* b12 = (const float*)d_in[6];
    const float* w20 = (const float*)d_in[7];  const float* b20 = (const float*)d_in[8];
    const float* w21 = (const float*)d_in[9];  const float* b21 = (const float*)d_in[10];
    const float* w22 = (const float*)d_in[11]; const float* b22 = (const float*)d_in[12];
    const float* w30 = (const float*)d_in[13]; const float* b30 = (const float*)d_in[14];
    const float* w31 = (const float*)d_in[15]; const float* b31 = (const float*)d_in[16];
    const float* w32 = (const float*)d_in[17]; const float* b32 = (const float*)d_in[18];
    const float* lw1 = (const float*)d_in[19]; const float* lb1 = (const float*)d_in[20];
    const float* lw2 = (const float*)d_in[21]; const float* lb2 = (const float*)d_in[22];
    const float* fw1 = (const float*)d_in[23]; const float* fb1 = (const float*)d_in[24];
    const float* fw2 = (const float*)d_in[25]; const float* fb2 = (const float*)d_in[26];
    const float* pos_mean = (const float*)d_in[27];
    const float* pos_std  = (const float*)d_in[28];
    const float* rot_mean = (const float*)d_in[29];
    const float* rot_std  = (const float*)d_in[30];
    float* out = (float*)d_out;

    cudaFuncSetAttribute(fps_kernel, cudaFuncAttributeMaxDynamicSharedMemorySize,
                         NPTS * 3 * 4 + 1024);

    fps_kernel<<<BATCH, 1024, NPTS * 3 * 4 + 768>>>(pts, NPTS, 512, 0);
    sa1_kernel<<<dim3(256, BATCH), 256>>>(pts, w10, b10, w11, b11, w12, b12);
    fps_kernel<<<BATCH, 512, 512 * 3 * 4 + 768>>>(pts, 512, 128, 1);
    // U2 = l1f @ w20[3:,:] + b20 (tensor cores)
    gemm_mma_kernel<<<dim3(BATCH * 512 / 64, 2), 256>>>(w20 + 3 * 128, b20, 128, 128, 3, 0);
    sa2_kernel<<<dim3(128, BATCH), 256>>>(w20, w21, b21, w22, b22);
    sa3build_kernel<<<BATCH, 256>>>();
    gemm_mma_kernel<<<dim3(BATCH * 128 / 64, 4), 256>>>(w30, b30, 259, 256, 0, 1);
    gemm_mma_kernel<<<dim3(BATCH * 128 / 64, 8), 256>>>(w31, b31, 256, 512, 1, 1);
    gemm_mma_kernel<<<dim3(BATCH * 128 / 64, 16), 256>>>(w32, b32, 512, 1024, 2, 1);
    heads_kernel<<<BATCH, 256>>>(lw1, lb1, lw2, lb2, fw1, fb1, fw2, fb2,
                                 pos_mean, pos_std, rot_mean, rot_std, out);
}

// round 9
// speedup vs baseline: 2.9296x; 1.2571x over previous
#include <cuda_runtime.h>
#include <cuda_bf16.h>
#include <stdint.h>
#include <math.h>

// ---------------------------------------------------------------------------
// PointNet++ grasp net forward. B=16, N=4096.
// FPS1 -> SA1 -> FPS2 -> U2(mma) -> SA2 -> SA3(mma, fused concat+maxpool) -> heads
// ---------------------------------------------------------------------------

#define BATCH 16
#define NPTS 4096

// exact f32 thresholds as JAX sees them (python double radius*radius -> f32)
#define R2A ((float)(0.2 * 0.2))
#define R2B ((float)(0.4 * 0.4))

// ------------------------- device scratch (static) -------------------------
__device__ __align__(16) float g_l1x[BATCH * 512 * 3];
__device__ __align__(16) float g_l1f[BATCH * 512 * 128];
__device__ __align__(16) float g_u2[BATCH * 512 * 128];   // l1f @ w20[3:] + b20
__device__ __align__(16) float g_l2x[BATCH * 128 * 3];
__device__ __align__(16) float g_l2f[BATCH * 128 * 256];
__device__ __align__(16) float g_h3a[BATCH * 128 * 256];
__device__ __align__(16) float g_h3b[BATCH * 128 * 512];
__device__ __align__(16) float g_pm[BATCH * 2 * 1024];    // 64-row maxpool partials

// ------------------------- mma / redux helpers -----------------------------
__device__ __forceinline__ uint32_t f2tf(float v) {
    uint32_t r;
    asm("cvt.rna.tf32.f32 %0, %1;" : "=r"(r) : "f"(v));
    return r;
}
__device__ __forceinline__ void mma_tf32(float* d, uint32_t a0, uint32_t a1,
                                         uint32_t a2, uint32_t a3,
                                         uint32_t b0, uint32_t b1) {
    asm volatile(
        "mma.sync.aligned.m16n8k8.row.col.f32.tf32.tf32.f32 "
        "{%0,%1,%2,%3}, {%4,%5,%6,%7}, {%8,%9}, {%0,%1,%2,%3};"
        : "+f"(d[0]), "+f"(d[1]), "+f"(d[2]), "+f"(d[3])
        : "r"(a0), "r"(a1), "r"(a2), "r"(a3), "r"(b0), "r"(b1));
}
__device__ __forceinline__ uint32_t redux_max_u32(uint32_t v) {
    uint32_t r;
    asm("redux.sync.max.u32 %0, %1, 0xffffffff;" : "=r"(r) : "r"(v));
    return r;
}
__device__ __forceinline__ uint32_t redux_min_u32(uint32_t v) {
    uint32_t r;
    asm("redux.sync.min.u32 %0, %1, 0xffffffff;" : "=r"(r) : "r"(v));
    return r;
}

// ---------------------------------------------------------------------------
// FPS: one block per batch. ONE barrier per iteration. Reductions use
// redux.sync on float bits (distances >= 0, so u32 order == float order);
// ties resolved by global min index via redux.min — exact jnp argmax
// semantics (first index). No FMA contraction in distances.
// ---------------------------------------------------------------------------
extern __shared__ float fps_sm[];

__global__ __launch_bounds__(1024) void fps_kernel(const float* __restrict__ pts_in,
                                                   int n, int S, int phase) {
    const int b = blockIdx.x;
    const float* p = (phase == 0 ? pts_in : g_l1x) + (size_t)b * n * 3;
    float* outxyz = (phase == 0 ? g_l1x : g_l2x);

    const int tid = threadIdx.x, BT = blockDim.x;
    float* sp = fps_sm;
    unsigned* rv = (unsigned*)(fps_sm + n * 3);  // 2x32 candidate val bits
    int* ri = (int*)(rv + 64);                   // 2x32 candidate idxs

    for (int e = tid; e < n * 3; e += BT) sp[e] = p[e];

    const int PT = n / BT;
    float px[4], py[4], pz[4], dd[4];
#pragma unroll
    for (int k = 0; k < 4; k++) {
        if (k < PT) {
            int i = tid + k * BT;
            px[k] = p[i * 3 + 0];
            py[k] = p[i * 3 + 1];
            pz[k] = p[i * 3 + 2];
            dd[k] = 1e10f;
        }
    }
    __syncthreads();

    const int lane = tid & 31, wid = tid >> 5, nw = BT >> 5;
    const int lsel = lane & (nw - 1);
    int far = 0;

    for (int s = 0; s < S; s++) {
        const float fx = sp[far * 3 + 0], fy = sp[far * 3 + 1], fz = sp[far * 3 + 2];
        if (tid == 0) {
            float* o = outxyz + ((size_t)b * S + s) * 3;
            o[0] = fx; o[1] = fy; o[2] = fz;
        }
        float bv = -1.0f;
        int bi = 0x7fffffff;
#pragma unroll
        for (int k = 0; k < 4; k++) {
            if (k < PT) {
                float dx = __fsub_rn(px[k], fx);
                float dy = __fsub_rn(py[k], fy);
                float dz = __fsub_rn(pz[k], fz);
                float d = __fadd_rn(__fadd_rn(__fmul_rn(dx, dx), __fmul_rn(dy, dy)),
                                    __fmul_rn(dz, dz));
                float ndv = fminf(dd[k], d);
                dd[k] = ndv;
                if (ndv > bv) { bv = ndv; bi = tid + k * BT; }  // keeps min idx on tie
            }
        }
        // warp reduce via redux: max val bits, then min idx among ties
        {
            uint32_t uv = __float_as_uint(bv);   // bv >= 0 always (PT >= 1)
            uint32_t vmax = redux_max_u32(uv);
            uint32_t ip = (uv == vmax) ? (uint32_t)bi : 0xffffffffu;
            uint32_t imin = redux_min_u32(ip);
            const int po = (s & 1) * 32;
            if (lane == 0) { rv[po + wid] = vmax; ri[po + wid] = (int)imin; }
        }
        __syncthreads();
        // block reduce (all warps redundantly -> all threads get far)
        {
            const int po = (s & 1) * 32;
            uint32_t v = rv[po + lsel];
            int i2 = ri[po + lsel];
            uint32_t vmax = redux_max_u32(v);
            uint32_t ip = (v == vmax) ? (uint32_t)i2 : 0xffffffffu;
            far = (int)redux_min_u32(ip);
        }
    }
}

// ---------------------------------------------------------------------------
// SA1: FOUR groups per block (256 thr). Ball query r=0.2 ns=32 over 4096 pts
// amortized over 4 centers; L1 (3->64) scalar; L2 (64->64) and
// L3 (64->128, fused per-group maxpool) on tf32 mma.
// 128 rows = 8 m16 tiles; 8 warps each own one m-tile, loop n.
// ---------------------------------------------------------------------------
#define P1 68  // padded pitch for 64-wide smem rows
#define SA1_SMEM ((384 + 16 + 2 * 128 * P1) * 4 + 4 * 128 * 4 + 128 * 4)

extern __shared__ float sa1_sm[];

__global__ __launch_bounds__(256) void sa1_kernel(
    const float* __restrict__ pts,
    const float* __restrict__ w10, const float* __restrict__ b10,
    const float* __restrict__ w11, const float* __restrict__ b11,
    const float* __restrict__ w12, const float* __restrict__ b12) {
    const int sp4 = blockIdx.x;  // groups sp4*4 .. sp4*4+3
    const int b = blockIdx.y;
    const int tid = threadIdx.x;
    const float* p = pts + (size_t)b * NPTS * 3;

    float* Ax = sa1_sm;                         // 384
    float* ctr = Ax + 384;                      // 16 (12 used)
    float* H1 = ctr + 16;                       // 128*P1 (reused as Pm[8][128])
    float* H2 = H1 + 128 * P1;                  // 128*P1
    unsigned* smask = (unsigned*)(H2 + 128 * P1);  // 4*128
    int* sel = (int*)(smask + 512);             // 128

    if (tid < 12) ctr[tid] = g_l1x[((size_t)b * 512 + sp4 * 4) * 3 + tid];
    __syncthreads();

    const int lane = tid & 31, warp = tid >> 5;
    {
        const float ax = ctr[0], ay = ctr[1], az = ctr[2];
        const float bx = ctr[3], by = ctr[4], bz = ctr[5];
        const float cx = ctr[6], cy = ctr[7], cz = ctr[8];
        const float ex = ctr[9], ey = ctr[10], ez = ctr[11];
        for (int w = warp; w < 128; w += 8) {
            int j = w * 32 + lane;
            float x = p[j * 3 + 0], y = p[j * 3 + 1], z = p[j * 3 + 2];
            float t0, t1, t2, d0, d1, d2, d3;
            t0 = __fsub_rn(ax, x); t1 = __fsub_rn(ay, y); t2 = __fsub_rn(az, z);
            d0 = __fadd_rn(__fadd_rn(__fmul_rn(t0, t0), __fmul_rn(t1, t1)), __fmul_rn(t2, t2));
            t0 = __fsub_rn(bx, x); t1 = __fsub_rn(by, y); t2 = __fsub_rn(bz, z);
            d1 = __fadd_rn(__fadd_rn(__fmul_rn(t0, t0), __fmul_rn(t1, t1)), __fmul_rn(t2, t2));
            t0 = __fsub_rn(cx, x); t1 = __fsub_rn(cy, y); t2 = __fsub_rn(cz, z);
            d2 = __fadd_rn(__fadd_rn(__fmul_rn(t0, t0), __fmul_rn(t1, t1)), __fmul_rn(t2, t2));
            t0 = __fsub_rn(ex, x); t1 = __fsub_rn(ey, y); t2 = __fsub_rn(ez, z);
            d3 = __fadd_rn(__fadd_rn(__fmul_rn(t0, t0), __fmul_rn(t1, t1)), __fmul_rn(t2, t2));
            unsigned m0 = __ballot_sync(0xffffffffu, !(d0 > R2A));
            unsigned m1 = __ballot_sync(0xffffffffu, !(d1 > R2A));
            unsigned m2 = __ballot_sync(0xffffffffu, !(d2 > R2A));
            unsigned m3 = __ballot_sync(0xffffffffu, !(d3 > R2A));
            if (lane == 0) {
                smask[w] = m0; smask[128 + w] = m1;
                smask[256 + w] = m2; smask[384 + w] = m3;
            }
        }
    }
    __syncthreads();
    if ((tid & 63) == 0) {  // tids 0,64,128,192 scan their group's mask
        int gs = tid >> 6;
        int cnt = 0;
        for (int w = 0; w < 128 && cnt < 32; w++) {
            unsigned m = smask[gs * 128 + w];
            while (m && cnt < 32) {
                int t = __ffs(m) - 1;
                m &= m - 1;
                sel[gs * 32 + cnt++] = w * 32 + t;
            }
        }
        int c0 = sel[gs * 32];
        for (int j = cnt; j < 32; j++) sel[gs * 32 + j] = c0;
    }
    __syncthreads();
    for (int e = tid; e < 384; e += 256) {
        int n = e / 3, c = e - n * 3;
        Ax[e] = p[sel[n] * 3 + c] - ctr[(n >> 5) * 3 + c];
    }
    __syncthreads();

    // L1: 3 -> 64 for 128 rows (32 outputs/thread)
#pragma unroll
    for (int r = 0; r < 32; r++) {
        int lin = r * 256 + tid;
        int n = lin >> 6, o = lin & 63;
        float a = b10[o] + Ax[n * 3 + 0] * w10[o] + Ax[n * 3 + 1] * w10[64 + o] +
                  Ax[n * 3 + 2] * w10[128 + o];
        H1[n * P1 + o] = fmaxf(a, 0.f);
    }
    __syncthreads();

    const int g = lane >> 2, q = lane & 3;
    const int m0 = warp * 16;

    // L2: 128x64x64 tf32 mma (warp = m-tile, full 64 cols) -> H2
    {
        float d[8][4] = {};
        for (int k0 = 0; k0 < 64; k0 += 8) {
            uint32_t a0 = f2tf(H1[(m0 + g) * P1 + k0 + q]);
            uint32_t a1 = f2tf(H1[(m0 + g + 8) * P1 + k0 + q]);
            uint32_t a2 = f2tf(H1[(m0 + g) * P1 + k0 + q + 4]);
            uint32_t a3 = f2tf(H1[(m0 + g + 8) * P1 + k0 + q + 4]);
#pragma unroll
            for (int nt = 0; nt < 8; nt++) {
                int n0 = nt * 8;
                uint32_t b0 = f2tf(w11[(k0 + q) * 64 + n0 + g]);
                uint32_t b1 = f2tf(w11[(k0 + q + 4) * 64 + n0 + g]);
                mma_tf32(d[nt], a0, a1, a2, a3, b0, b1);
            }
        }
        __syncthreads();  // H1 reads done before Pm (=H1) writes in L3
#pragma unroll
        for (int nt = 0; nt < 8; nt++) {
            int c0 = nt * 8 + q * 2;
            float bb0 = b11[c0], bb1 = b11[c0 + 1];
            H2[(m0 + g) * P1 + c0] = fmaxf(d[nt][0] + bb0, 0.f);
            H2[(m0 + g) * P1 + c0 + 1] = fmaxf(d[nt][1] + bb1, 0.f);
            H2[(m0 + g + 8) * P1 + c0] = fmaxf(d[nt][2] + bb0, 0.f);
            H2[(m0 + g + 8) * P1 + c0 + 1] = fmaxf(d[nt][3] + bb1, 0.f);
        }
    }
    __syncthreads();

    // L3: 128x128x64 tf32 mma in two 64-col passes with fused 16-row maxpool
    float* Pm = H1;  // [8][128]
    for (int pass = 0; pass < 2; pass++) {
        float d[8][4] = {};
        for (int k0 = 0; k0 < 64; k0 += 8) {
            uint32_t a0 = f2tf(H2[(m0 + g) * P1 + k0 + q]);
            uint32_t a1 = f2tf(H2[(m0 + g + 8) * P1 + k0 + q]);
            uint32_t a2 = f2tf(H2[(m0 + g) * P1 + k0 + q + 4]);
            uint32_t a3 = f2tf(H2[(m0 + g + 8) * P1 + k0 + q + 4]);
#pragma unroll
            for (int nt = 0; nt < 8; nt++) {
                int n0 = pass * 64 + nt * 8;
                uint32_t b0 = f2tf(w12[(k0 + q) * 128 + n0 + g]);
                uint32_t b1 = f2tf(w12[(k0 + q + 4) * 128 + n0 + g]);
                mma_tf32(d[nt], a0, a1, a2, a3, b0, b1);
            }
        }
#pragma unroll
        for (int nt = 0; nt < 8; nt++) {
            float m0v = fmaxf(d[nt][0], d[nt][2]);
            float m1v = fmaxf(d[nt][1], d[nt][3]);
#pragma unroll
            for (int off = 4; off < 32; off <<= 1) {
                m0v = fmaxf(m0v, __shfl_xor_sync(0xffffffffu, m0v, off));
                m1v = fmaxf(m1v, __shfl_xor_sync(0xffffffffu, m1v, off));
            }
            if (g == 0) {
                int c0 = pass * 64 + nt * 8 + q * 2;
                Pm[warp * 128 + c0] = m0v;
                Pm[warp * 128 + c0 + 1] = m1v;
            }
        }
    }
    __syncthreads();
    for (int e = tid; e < 512; e += 256) {
        int h = e >> 7, o = e & 127;
        float m = fmaxf(Pm[(2 * h) * 128 + o], Pm[(2 * h + 1) * 128 + o]);
        g_l1f[((size_t)b * 512 + sp4 * 4 + h) * 128 + o] = fmaxf(m + b12[o], 0.f);
    }
}

// ---------------------------------------------------------------------------
// SA2: per (b,s): ball query (r=0.4, ns=64) over 512 pts.
// L1 via precomputed U2 gather; L2/L3 on tf32 mma (fused maxpool).
// ---------------------------------------------------------------------------
#define P2 132

__global__ __launch_bounds__(256) void sa2_kernel(
    const float* __restrict__ w20,
    const float* __restrict__ w21, const float* __restrict__ b21,
    const float* __restrict__ w22, const float* __restrict__ b22) {
    const int s = blockIdx.x, b = blockIdx.y;
    const int tid = threadIdx.x;
    const float* px = g_l1x + (size_t)b * 512 * 3;

    __shared__ __align__(16) float H[64 * P2];
    __shared__ float Pm[4 * 256];
    __shared__ unsigned smask[16];
    __shared__ int sel[64];
    __shared__ float ctr[3];
    __shared__ float dx3[64 * 3];

    if (tid < 3) ctr[tid] = g_l2x[((size_t)b * 128 + s) * 3 + tid];
    __syncthreads();
    const float cx = ctr[0], cy = ctr[1], cz = ctr[2];

    const int lane = tid & 31, warp = tid >> 5;
    for (int w = warp; w < 16; w += 8) {
        int j = w * 32 + lane;
        float dx = __fsub_rn(cx, px[j * 3 + 0]);
        float dy = __fsub_rn(cy, px[j * 3 + 1]);
        float dz = __fsub_rn(cz, px[j * 3 + 2]);
        float d = __fadd_rn(__fadd_rn(__fmul_rn(dx, dx), __fmul_rn(dy, dy)),
                            __fmul_rn(dz, dz));
        unsigned m = __ballot_sync(0xffffffffu, !(d > R2B));
        if (lane == 0) smask[w] = m;
    }
    __syncthreads();
    if (tid == 0) {
        int cnt = 0;
        for (int w = 0; w < 16 && cnt < 64; w++) {
            unsigned m = smask[w];
            while (m && cnt < 64) {
                int t = __ffs(m) - 1;
                m &= m - 1;
                sel[cnt++] = w * 32 + t;
            }
        }
        int c0 = sel[0];
        for (int j = cnt; j < 64; j++) sel[j] = c0;
    }
    __syncthreads();
    if (tid < 192) {
        int n = tid / 3, c = tid - n * 3;
        float cc = (c == 0) ? cx : ((c == 1) ? cy : cz);
        dx3[tid] = px[sel[n] * 3 + c] - cc;
    }
    __syncthreads();

    // L1: gather U2 + xyz contribution, relu
    {
        const int o0 = (tid & 31) * 4, n0 = (tid >> 5) * 8;
        float4 wxv = *(const float4*)(w20 + o0);
        float4 wyv = *(const float4*)(w20 + 128 + o0);
        float4 wzv = *(const float4*)(w20 + 256 + o0);
#pragma unroll
        for (int i = 0; i < 8; i++) {
            int n = n0 + i;
            float ddx = dx3[n * 3 + 0], ddy = dx3[n * 3 + 1], ddz = dx3[n * 3 + 2];
            float4 u = *(const float4*)(g_u2 + ((size_t)b * 512 + sel[n]) * 128 + o0);
            float4 r;
            r.x = fmaxf(u.x + ddx * wxv.x + ddy * wyv.x + ddz * wzv.x, 0.f);
            r.y = fmaxf(u.y + ddx * wxv.y + ddy * wyv.y + ddz * wzv.y, 0.f);
            r.z = fmaxf(u.z + ddx * wxv.z + ddy * wyv.z + ddz * wzv.z, 0.f);
            r.w = fmaxf(u.w + ddx * wxv.w + ddy * wyv.w + ddz * wzv.w, 0.f);
            *(float4*)(H + n * P2 + o0) = r;
        }
    }
    __syncthreads();

    const int g = lane >> 2, q = lane & 3;
    const int mi = warp >> 1, nh = warp & 1;
    const int m0 = mi * 16;

    // L2: 64x128x128 tf32 mma, in-place H update
    {
        float d[8][4] = {};
        for (int k0 = 0; k0 < 128; k0 += 8) {
            uint32_t a0 = f2tf(H[(m0 + g) * P2 + k0 + q]);
            uint32_t a1 = f2tf(H[(m0 + g + 8) * P2 + k0 + q]);
            uint32_t a2 = f2tf(H[(m0 + g) * P2 + k0 + q + 4]);
            uint32_t a3 = f2tf(H[(m0 + g + 8) * P2 + k0 + q + 4]);
#pragma unroll
            for (int nt = 0; nt < 8; nt++) {
                int n0 = nh * 64 + nt * 8;
                uint32_t b0 = f2tf(w21[(k0 + q) * 128 + n0 + g]);
                uint32_t b1 = f2tf(w21[(k0 + q + 4) * 128 + n0 + g]);
                mma_tf32(d[nt], a0, a1, a2, a3, b0, b1);
            }
        }
        __syncthreads();
#pragma unroll
        for (int nt = 0; nt < 8; nt++) {
            int c0 = nh * 64 + nt * 8 + q * 2;
            float bb0 = b21[c0], bb1 = b21[c0 + 1];
            H[(m0 + g) * P2 + c0] = fmaxf(d[nt][0] + bb0, 0.f);
            H[(m0 + g) * P2 + c0 + 1] = fmaxf(d[nt][1] + bb1, 0.f);
            H[(m0 + g + 8) * P2 + c0] = fmaxf(d[nt][2] + bb0, 0.f);
            H[(m0 + g + 8) * P2 + c0 + 1] = fmaxf(d[nt][3] + bb1, 0.f);
        }
    }
    __syncthreads();

    // L3: 64x256x128 tf32 mma in two 128-col passes, fused maxpool -> Pm
    for (int pass = 0; pass < 2; pass++) {
        float d[8][4] = {};
        for (int k0 = 0; k0 < 128; k0 += 8) {
            uint32_t a0 = f2tf(H[(m0 + g) * P2 + k0 + q]);
            uint32_t a1 = f2tf(H[(m0 + g + 8) * P2 + k0 + q]);
            uint32_t a2 = f2tf(H[(m0 + g) * P2 + k0 + q + 4]);
            uint32_t a3 = f2tf(H[(m0 + g + 8) * P2 + k0 + q + 4]);
#pragma unroll
            for (int nt = 0; nt < 8; nt++) {
                int n0 = pass * 128 + nh * 64 + nt * 8;
                uint32_t b0 = f2tf(w22[(k0 + q) * 256 + n0 + g]);
                uint32_t b1 = f2tf(w22[(k0 + q + 4) * 256 + n0 + g]);
                mma_tf32(d[nt], a0, a1, a2, a3, b0, b1);
            }
        }
#pragma unroll
        for (int nt = 0; nt < 8; nt++) {
            float m0v = fmaxf(d[nt][0], d[nt][2]);
            float m1v = fmaxf(d[nt][1], d[nt][3]);
#pragma unroll
            for (int off = 4; off < 32; off <<= 1) {
                m0v = fmaxf(m0v, __shfl_xor_sync(0xffffffffu, m0v, off));
                m1v = fmaxf(m1v, __shfl_xor_sync(0xffffffffu, m1v, off));
            }
            if (g == 0) {
                int c0 = pass * 128 + nh * 64 + nt * 8 + q * 2;
                Pm[mi * 256 + c0] = m0v;
                Pm[mi * 256 + c0 + 1] = m1v;
            }
        }
    }
    __syncthreads();
    {
        int o = tid;
        float m = fmaxf(fmaxf(Pm[o], Pm[256 + o]), fmaxf(Pm[512 + o], Pm[768 + o]));
        g_l2f[((size_t)b * 128 + s) * 256 + o] = fmaxf(m + b22[o], 0.f);
    }
}

// ---------------------------------------------------------------------------
// tf32 mma GEMM + bias (+relu), batch flattened into M.
// which: 0 concat(l2x,l2f)->h3a (K=259,O=256) [A built on the fly],
//        1 h3a->h3b (256,512), 2 h3b->maxpool partials g_pm (512,1024),
//        3 l1f->u2 (128,128)
// ---------------------------------------------------------------------------
__global__ __launch_bounds__(256) void gemm_mma_kernel(const float* __restrict__ W,
                                                       const float* __restrict__ bias,
                                                       int K, int O, int which, int dorelu) {
    const int mblk = blockIdx.x, oblk = blockIdx.y;
    const float* A = nullptr;
    float* C = nullptr;
    if (which == 1) { A = g_h3a; C = g_h3b; }
    else if (which == 2) { A = g_h3b; }
    else if (which == 3) { A = g_l1f; C = g_u2; }
    else { C = g_h3a; }

    const int row0 = mblk * 64;
    const int tid = threadIdx.x, lane = tid & 31, warp = tid >> 5;
    const int g = lane >> 2, q = lane & 3;
    const int mi = warp >> 1, nh = warp & 1, m0 = mi * 16;
    const int ob = oblk * 64;

    __shared__ __align__(16) float As[64 * 36];
    __shared__ float Pms[4 * 64];
    float d[4][4] = {};
    for (int kb = 0; kb < K; kb += 32) {
        const int w = min(32, K - kb);
        __syncthreads();
        if (which == 0) {
            for (int e = tid; e < 64 * 32; e += 256) {
                int r = e >> 5, cc = e & 31;
                int col = kb + cc;
                float v = 0.f;
                if (col < K) {
                    int row = row0 + r, bb = row >> 7, nn = row & 127;
                    v = (col < 3) ? g_l2x[((size_t)bb * 128 + nn) * 3 + col]
                                  : g_l2f[((size_t)bb * 128 + nn) * 256 + col - 3];
                }
                As[r * 36 + cc] = v;
            }
        } else {
            for (int e = tid; e < 64 * 32; e += 256) {
                int r = e >> 5, cc = e & 31;
                As[r * 36 + cc] = (cc < w) ? A[(size_t)(row0 + r) * K + kb + cc] : 0.f;
            }
        }
        __syncthreads();
#pragma unroll
        for (int k0 = 0; k0 < 32; k0 += 8) {
            uint32_t a0 = f2tf(As[(m0 + g) * 36 + k0 + q]);
            uint32_t a1 = f2tf(As[(m0 + g + 8) * 36 + k0 + q]);
            uint32_t a2 = f2tf(As[(m0 + g) * 36 + k0 + q + 4]);
            uint32_t a3 = f2tf(As[(m0 + g + 8) * 36 + k0 + q + 4]);
            int kr0 = kb + k0 + q, kr1 = kb + k0 + q + 4;
            int kc0 = kr0 < K ? kr0 : K - 1;
            int kc1 = kr1 < K ? kr1 : K - 1;
#pragma unroll
            for (int nt = 0; nt < 4; nt++) {
                int n0 = ob + nh * 32 + nt * 8;
                uint32_t b0 = f2tf(W[(size_t)kc0 * O + n0 + g]);
                uint32_t b1 = f2tf(W[(size_t)kc1 * O + n0 + g]);
                mma_tf32(d[nt], a0, a1, a2, a3, b0, b1);
            }
        }
    }
    if (which != 2) {
#pragma unroll
        for (int nt = 0; nt < 4; nt++) {
            int c0 = ob + nh * 32 + nt * 8 + q * 2;
            float bb0 = bias[c0], bb1 = bias[c0 + 1];
            float v00 = d[nt][0] + bb0, v01 = d[nt][1] + bb1;
            float v10 = d[nt][2] + bb0, v11 = d[nt][3] + bb1;
            if (dorelu) {
                v00 = fmaxf(v00, 0.f); v01 = fmaxf(v01, 0.f);
                v10 = fmaxf(v10, 0.f); v11 = fmaxf(v11, 0.f);
            }
            C[(size_t)(row0 + m0 + g) * O + c0] = v00;
            C[(size_t)(row0 + m0 + g) * O + c0 + 1] = v01;
            C[(size_t)(row0 + m0 + g + 8) * O + c0] = v10;
            C[(size_t)(row0 + m0 + g + 8) * O + c0 + 1] = v11;
        }
    } else {
#pragma unroll
        for (int nt = 0; nt < 4; nt++) {
            int c0l = nh * 32 + nt * 8 + q * 2;
            int c0 = ob + c0l;
            float bb0 = bias[c0], bb1 = bias[c0 + 1];
            float m0v = fmaxf(fmaxf(d[nt][0] + bb0, 0.f), fmaxf(d[nt][2] + bb0, 0.f));
            float m1v = fmaxf(fmaxf(d[nt][1] + bb1, 0.f), fmaxf(d[nt][3] + bb1, 0.f));
#pragma unroll
            for (int off = 4; off < 32; off <<= 1) {
                m0v = fmaxf(m0v, __shfl_xor_sync(0xffffffffu, m0v, off));
                m1v = fmaxf(m1v, __shfl_xor_sync(0xffffffffu, m1v, off));
            }
            if (g == 0) {
                Pms[mi * 64 + c0l] = m0v;
                Pms[mi * 64 + c0l + 1] = m1v;
            }
        }
        __syncthreads();
        if (tid < 64) {
            float m = fmaxf(fmaxf(Pms[tid], Pms[64 + tid]),
                            fmaxf(Pms[128 + tid], Pms[192 + tid]));
            g_pm[(size_t)mblk * 1024 + ob + tid] = m;
        }
    }
}

// ---------------------------------------------------------------------------
// Heads: combine 2 maxpool partials -> g; then FC heads.
// ---------------------------------------------------------------------------
__global__ __launch_bounds__(256) void heads_kernel(
    const float* __restrict__ lw1, const float* __restrict__ lb1,
    const float* __restrict__ lw2, const float* __restrict__ lb2,
    const float* __restrict__ fw1, const float* __restrict__ fb1,
    const float* __restrict__ fw2, const float* __restrict__ fb2,
    const float* __restrict__ pos_mean, const float* __restrict__ pos_std,
    const float* __restrict__ rot_mean, const float* __restrict__ rot_std,
    float* __restrict__ out) {
    const int b = blockIdx.x;
    const int tid = threadIdx.x;
    __shared__ float gs[1024], h1s[256], f1s[512], res[18], lab[2];
    for (int e = tid; e < 1024; e += 256)
        gs[e] = fmaxf(g_pm[(size_t)(b * 2) * 1024 + e],
                      g_pm[(size_t)(b * 2 + 1) * 1024 + e]);
    __syncthreads();
#pragma unroll
    for (int rep = 0; rep < 2; rep++) {
        int o = tid + rep * 256;
        float acc = fb1[o];
        for (int k = 0; k < 1024; k++) acc += gs[k] * fw1[k * 512 + o];
        f1s[o] = fmaxf(acc, 0.f);
    }
    {
        int o = tid;
        float acc = lb1[o];
        for (int k = 0; k < 1024; k++) acc += gs[k] * lw1[k * 256 + o];
        h1s[o] = fmaxf(acc, 0.f);
    }
    __syncthreads();
    if (tid < 18) {
        float acc = fb2[tid];
        for (int k = 0; k < 512; k++) acc += f1s[k] * fw2[k * 18 + tid];
        res[tid] = acc;
    } else if (tid < 20) {
        int j = tid - 18;
        float acc = lb2[j];
        for (int k = 0; k < 256; k++) acc += h1s[k] * lw2[k * 2 + j];
        lab[j] = 1.f / (1.f + expf(-acc));
    }
    __syncthreads();
    if (tid < 20) {
        float v;
        if (tid < 2) v = lab[tid];
        else if (tid < 5) { int i = tid - 2; v = res[i] * pos_std[i] + pos_mean[i]; }
        else if (tid < 11) { int i = tid - 5; v = res[3 + i] * rot_std[i] + rot_mean[i]; }
        else if (tid < 14) { int i = tid - 11; v = res[9 + i] * pos_std[i] + pos_mean[i]; }
        else { int i = tid - 14; v = res[12 + i] * rot_std[i] + rot_mean[i]; }
        out[b * 20 + tid] = v;
    }
}

// ---------------------------------------------------------------------------
extern "C" void kernel_launch(void* const* d_in, const int* in_sizes, int n_in,
                              void* d_out, int out_size) {
    (void)in_sizes; (void)n_in; (void)out_size;
    const float* pts = (const float*)d_in[0];
    const float* w10 = (const float*)d_in[1];  const float* b10 = (const float*)d_in[2];
    const float* w11 = (const float*)d_in[3];  const float* b11 = (const float*)d_in[4];
    const float* w12 = (const float*)d_in[5];  const float* b12 = (const float*)d_in[6];
    const float* w20 = (const float*)d_in[7];  const float* b20 = (const float*)d_in[8];
    const float* w21 = (const float*)d_in[9];  const float* b21 = (const float*)d_in[10];
    const float* w22 = (const float*)d_in[11]; const float* b22 = (const float*)d_in[12];
    const float* w30 = (const float*)d_in[13]; const float* b30 = (const float*)d_in[14];
    const float* w31 = (const float*)d_in[15]; const float* b31 = (const float*)d_in[16];
    const float* w32 = (const float*)d_in[17]; const float* b32 = (const float*)d_in[18];
    const float* lw1 = (const float*)d_in[19]; const float* lb1 = (const float*)d_in[20];
    const float* lw2 = (const float*)d_in[21]; const float* lb2 = (const float*)d_in[22];
    const float* fw1 = (const float*)d_in[23]; const float* fb1 = (const float*)d_in[24];
    const float* fw2 = (const float*)d_in[25]; const float* fb2 = (const float*)d_in[26];
    const float* pos_mean = (const float*)d_in[27];
    const float* pos_std  = (const float*)d_in[28];
    const float* rot_mean = (const float*)d_in[29];
    const float* rot_std  = (const float*)d_in[30];
    float* out = (float*)d_out;

    cudaFuncSetAttribute(fps_kernel, cudaFuncAttributeMaxDynamicSharedMemorySize,
                         NPTS * 3 * 4 + 1024);
    cudaFuncSetAttribute(sa1_kernel, cudaFuncAttributeMaxDynamicSharedMemorySize,
                         SA1_SMEM + 256);

    fps_kernel<<<BATCH, 1024, NPTS * 3 * 4 + 768>>>(pts, NPTS, 512, 0);
    sa1_kernel<<<dim3(128, BATCH), 256, SA1_SMEM>>>(pts, w10, b10, w11, b11, w12, b12);
    fps_kernel<<<BATCH, 512, 512 * 3 * 4 + 768>>>(pts, 512, 128, 1);
    gemm_mma_kernel<<<dim3(BATCH * 512 / 64, 2), 256>>>(w20 + 3 * 128, b20, 128, 128, 3, 0);
    sa2_kernel<<<dim3(128, BATCH), 256>>>(w20, w21, b21, w22, b22);
    gemm_mma_kernel<<<dim3(BATCH * 128 / 64, 4), 256>>>(w30, b30, 259, 256, 0, 1);
    gemm_mma_kernel<<<dim3(BATCH * 128 / 64, 8), 256>>>(w31, b31, 256, 512, 1, 1);
    gemm_mma_kernel<<<dim3(BATCH * 128 / 64, 16), 256>>>(w32, b32, 512, 1024, 2, 1);
    heads_kernel<<<BATCH, 256>>>(lw1, lb1, lw2, lb2, fw1, fb1, fw2, fb2,
                                 pos_mean, pos_std, rot_mean, rot_std, out);
}